// round 14
// baseline (speedup 1.0000x reference)
#include <cuda_runtime.h>
#include <cuda_bf16.h>
#include <math.h>

#define N_NODES 100000
#define N_EDGES 1600000
#define HID 128
#define HEADS 8
#define N_LAYERS 4
#define IN_DIM 32
#define N_CLASSES 16

// ---------------- scratch (device globals; no allocation allowed) ----------------
__device__ float g_q[N_NODES * HID];
__device__ __nv_bfloat16 g_kv[N_NODES * 2 * HID];   // k then v, bf16, per node
__device__ float g_t0[N_NODES * 64];
__device__ float g_t1[N_NODES * 32];
__device__ int g_rowptr[N_NODES + 1];

// bf16 hi/lo activation buffers (hi+lo reconstructs ~fp32)
__device__ __nv_bfloat16 g_h_hi[N_NODES * HID];
__device__ __nv_bfloat16 g_h_lo[N_NODES * HID];
__device__ __nv_bfloat16 g_attn_hi[N_NODES * HID];
__device__ __nv_bfloat16 g_attn_lo[N_NODES * HID];
__device__ __nv_bfloat16 g_mid_hi[N_NODES * 2 * HID];
__device__ __nv_bfloat16 g_mid_lo[N_NODES * 2 * HID];

// bf16 hi/lo transposed weights (B^T layout: [rows=N][cols=K])
__device__ __nv_bfloat16 g_wqkv_hi[N_LAYERS * 3 * HID * HID];
__device__ __nv_bfloat16 g_wqkv_lo[N_LAYERS * 3 * HID * HID];
__device__ __nv_bfloat16 g_wo_hi[N_LAYERS * HID * HID];
__device__ __nv_bfloat16 g_wo_lo[N_LAYERS * HID * HID];
__device__ __nv_bfloat16 g_w1_hi[N_LAYERS * 2 * HID * HID];
__device__ __nv_bfloat16 g_w1_lo[N_LAYERS * 2 * HID * HID];
__device__ __nv_bfloat16 g_w2_hi[N_LAYERS * HID * 2 * HID];
__device__ __nv_bfloat16 g_w2_lo[N_LAYERS * HID * 2 * HID];
__device__ __nv_bfloat16 g_m0_hi[64 * HID];
__device__ __nv_bfloat16 g_m0_lo[64 * HID];

// ---------------- helpers ----------------
__device__ __forceinline__ void split_bf16(float x, __nv_bfloat16& hi, __nv_bfloat16& lo) {
    hi = __float2bfloat16(x);
    lo = __float2bfloat16(x - __bfloat162float(hi));
}
__device__ __forceinline__ void ldmx4(unsigned r[4], const void* p) {
    unsigned addr = (unsigned)__cvta_generic_to_shared(p);
    asm volatile("ldmatrix.sync.aligned.m8n8.x4.shared.b16 {%0,%1,%2,%3}, [%4];"
                 : "=r"(r[0]), "=r"(r[1]), "=r"(r[2]), "=r"(r[3])
                 : "r"(addr));
}
__device__ __forceinline__ void mma16816(float d[4], const unsigned a[4],
                                         unsigned b0, unsigned b1) {
    asm volatile(
        "mma.sync.aligned.m16n8k16.row.col.f32.bf16.bf16.f32 "
        "{%0,%1,%2,%3},{%4,%5,%6,%7},{%8,%9},{%0,%1,%2,%3};"
        : "+f"(d[0]), "+f"(d[1]), "+f"(d[2]), "+f"(d[3])
        : "r"(a[0]), "r"(a[1]), "r"(a[2]), "r"(a[3]), "r"(b0), "r"(b1));
}
__device__ __forceinline__ void cp16(unsigned dst, const void* src, int sz) {
    asm volatile("cp.async.cg.shared.global [%0], [%1], 16, %2;"
                 :: "r"(dst), "l"(src), "r"(sz));
}
__device__ __forceinline__ void fma2(unsigned long long& d, unsigned long long a,
                                     unsigned long long b, unsigned long long c) {
    asm("fma.rn.f32x2 %0, %1, %2, %3;" : "=l"(d) : "l"(a), "l"(b), "l"(c));
}
__device__ __forceinline__ unsigned long long pack2(float x) {
    unsigned long long d;
    unsigned u = __float_as_uint(x);
    asm("mov.b64 %0, {%1, %2};" : "=l"(d) : "r"(u), "r"(u));
    return d;
}
__device__ __forceinline__ void unpack2(unsigned long long v, float& lo, float& hi) {
    unsigned a, b;
    asm("mov.b64 {%0, %1}, %2;" : "=r"(a), "=r"(b) : "l"(v));
    lo = __uint_as_float(a);
    hi = __uint_as_float(b);
}
// pack 4 floats into hi-uint2 and lo-uint2 (bf16x2 pairs)
__device__ __forceinline__ void pack_hilo4(const float* xs, uint2& phi, uint2& plo) {
    __nv_bfloat16 h[4], l[4];
#pragma unroll
    for (int i = 0; i < 4; i++) split_bf16(xs[i], h[i], l[i]);
    __nv_bfloat162 h01, h23, l01, l23;
    h01.x = h[0]; h01.y = h[1];
    h23.x = h[2]; h23.y = h[3];
    l01.x = l[0]; l01.y = l[1];
    l23.x = l[2]; l23.y = l[3];
    phi.x = *(unsigned*)&h01;
    phi.y = *(unsigned*)&h23;
    plo.x = *(unsigned*)&l01;
    plo.y = *(unsigned*)&l23;
}
__device__ __forceinline__ float2 bf2f(unsigned u) {
    return __bfloat1622float2(*(__nv_bfloat162*)&u);
}

// ---------------- weight split+transpose (consolidated into 2 launches) ----------------
__device__ __forceinline__ void splitw_store(const float* W, __nv_bfloat16* hi,
                                             __nv_bfloat16* lo, int idx, int K, int N,
                                             int lsRows, int rowOff) {
    int l = idx / (K * N);
    int rem = idx - l * K * N;
    int k = rem / N;
    int n = rem - k * N;
    float x = W[idx];
    __nv_bfloat16 h, lw;
    split_bf16(x, h, lw);
    size_t d = ((size_t)(l * lsRows + rowOff + n)) * K + k;
    hi[d] = h;
    lo[d] = lw;
}

// kernel A: Wq, Wk, Wv, Wo, mW0
#define SQ_TOT (N_LAYERS * HID * HID)
__global__ void splitw_a_kernel(const float* __restrict__ Wq, const float* __restrict__ Wk,
                                const float* __restrict__ Wv, const float* __restrict__ Wo,
                                const float* __restrict__ mW0,
                                __nv_bfloat16* __restrict__ qkv_hi, __nv_bfloat16* __restrict__ qkv_lo,
                                __nv_bfloat16* __restrict__ wo_hi, __nv_bfloat16* __restrict__ wo_lo,
                                __nv_bfloat16* __restrict__ m0_hi, __nv_bfloat16* __restrict__ m0_lo) {
    int idx = blockIdx.x * blockDim.x + threadIdx.x;
    if (idx < SQ_TOT) {
        splitw_store(Wq, qkv_hi, qkv_lo, idx, HID, HID, 3 * HID, 0);
        return;
    }
    idx -= SQ_TOT;
    if (idx < SQ_TOT) {
        splitw_store(Wk, qkv_hi, qkv_lo, idx, HID, HID, 3 * HID, HID);
        return;
    }
    idx -= SQ_TOT;
    if (idx < SQ_TOT) {
        splitw_store(Wv, qkv_hi, qkv_lo, idx, HID, HID, 3 * HID, 2 * HID);
        return;
    }
    idx -= SQ_TOT;
    if (idx < SQ_TOT) {
        splitw_store(Wo, wo_hi, wo_lo, idx, HID, HID, HID, 0);
        return;
    }
    idx -= SQ_TOT;
    if (idx < HID * 64) {
        splitw_store(mW0, m0_hi, m0_lo, idx, HID, 64, 64, 0);
    }
}

// kernel B: W1, W2
#define RT_TOT (N_LAYERS * HID * 2 * HID)
__global__ void splitw_b_kernel(const float* __restrict__ W1, const float* __restrict__ W2,
                                __nv_bfloat16* __restrict__ w1_hi, __nv_bfloat16* __restrict__ w1_lo,
                                __nv_bfloat16* __restrict__ w2_hi, __nv_bfloat16* __restrict__ w2_lo) {
    int idx = blockIdx.x * blockDim.x + threadIdx.x;
    if (idx < RT_TOT) {
        splitw_store(W1, w1_hi, w1_lo, idx, HID, 2 * HID, 2 * HID, 0);
        return;
    }
    idx -= RT_TOT;
    if (idx < RT_TOT) {
        splitw_store(W2, w2_hi, w2_lo, idx, 2 * HID, HID, HID, 0);
    }
}

// ---------------- embedding gather (hi/lo, vectorized stores) ----------------
__global__ void embed_kernel(const int* __restrict__ feat, const float* __restrict__ emb,
                             __nv_bfloat16* __restrict__ hhi, __nv_bfloat16* __restrict__ hlo) {
    int idx = blockIdx.x * blockDim.x + threadIdx.x;
    if (idx >= N_NODES * 32) return;
    int n = idx >> 5, c4 = idx & 31;
    int f = feat[n];
    float4 v = ((const float4*)emb)[f * 32 + c4];
    float xs[4] = {v.x, v.y, v.z, v.w};
    uint2 phi, plo;
    pack_hilo4(xs, phi, plo);
    size_t base = (size_t)n * HID + c4 * 4;
    *(uint2*)&hhi[base] = phi;
    *(uint2*)&hlo[base] = plo;
}

// ---------------- CSR row pointers from sorted edge_dst ----------------
__global__ void rowptr_kernel(const int* __restrict__ dst, int* __restrict__ rp) {
    int n = blockIdx.x * blockDim.x + threadIdx.x;
    if (n > N_NODES) return;
    if (n == N_NODES) { rp[n] = N_EDGES; return; }
    int lo = 0, hi = N_EDGES;
    while (lo < hi) {
        int mid = (lo + hi) >> 1;
        if (dst[mid] < n) lo = mid + 1; else hi = mid;
    }
    rp[n] = lo;
}

// ---------------- per-node attention: software-pipelined 4-edge batches ----------------
__device__ __forceinline__ float edge_score(float4 qv, float2 k0, float2 k1) {
    float s = k0.x * qv.x + k0.y * qv.y + k1.x * qv.z + k1.y * qv.w;
    s += __shfl_xor_sync(0xffffffffu, s, 1);
    s += __shfl_xor_sync(0xffffffffu, s, 2);
    s *= 0.25f;
    s = fminf(fmaxf(s, -5.0f), 5.0f);
    return __expf(s);
}

// load 4 edges' k/v rows into named registers
#define ATTN_LOAD(K0, K1, K2, K3, V0, V1, V2, V3, eb)                       \
    {                                                                       \
        int s0 = __ldg(esrc + (eb));                                        \
        int s1 = __ldg(esrc + (eb) + 1);                                    \
        int s2 = __ldg(esrc + (eb) + 2);                                    \
        int s3 = __ldg(esrc + (eb) + 3);                                    \
        const __nv_bfloat16* b0 = kv + (size_t)s0 * 256 + lane * 4;         \
        const __nv_bfloat16* b1 = kv + (size_t)s1 * 256 + lane * 4;         \
        const __nv_bfloat16* b2 = kv + (size_t)s2 * 256 + lane * 4;         \
        const __nv_bfloat16* b3 = kv + (size_t)s3 * 256 + lane * 4;         \
        K0 = *(const uint2*)b0;                                             \
        K1 = *(const uint2*)b1;                                             \
        K2 = *(const uint2*)b2;                                             \
        K3 = *(const uint2*)b3;                                             \
        V0 = *(const uint2*)(b0 + 128);                                     \
        V1 = *(const uint2*)(b1 + 128);                                     \
        V2 = *(const uint2*)(b2 + 128);                                     \
        V3 = *(const uint2*)(b3 + 128);                                     \
    }

// compute on a loaded batch (same op order as R13 -> identical numerics)
#define ATTN_COMPUTE(K0, K1, K2, K3, V0, V1, V2, V3)                        \
    {                                                                       \
        float sc0 = edge_score(qv, bf2f(K0.x), bf2f(K0.y));                 \
        float sc1 = edge_score(qv, bf2f(K1.x), bf2f(K1.y));                 \
        float sc2 = edge_score(qv, bf2f(K2.x), bf2f(K2.y));                 \
        float sc3 = edge_score(qv, bf2f(K3.x), bf2f(K3.y));                 \
        z0 += sc0 + sc2;                                                    \
        z1 += sc1 + sc3;                                                    \
        float2 v00 = bf2f(V0.x), v01 = bf2f(V0.y);                          \
        float2 v10 = bf2f(V1.x), v11 = bf2f(V1.y);                          \
        float2 v20 = bf2f(V2.x), v21 = bf2f(V2.y);                          \
        float2 v30 = bf2f(V3.x), v31 = bf2f(V3.y);                          \
        accA.x += sc0 * v00.x + sc2 * v20.x;                                \
        accA.y += sc0 * v00.y + sc2 * v20.y;                                \
        accA.z += sc0 * v01.x + sc2 * v21.x;                                \
        accA.w += sc0 * v01.y + sc2 * v21.y;                                \
        accB.x += sc1 * v10.x + sc3 * v30.x;                                \
        accB.y += sc1 * v10.y + sc3 * v30.y;                                \
        accB.z += sc1 * v11.x + sc3 * v31.x;                                \
        accB.w += sc1 * v11.y + sc3 * v31.y;                                \
    }

__global__ void attn_kernel(const float* __restrict__ q, const __nv_bfloat16* __restrict__ kv,
                            const int* __restrict__ rp, const int* __restrict__ esrc,
                            __nv_bfloat16* __restrict__ ohi, __nv_bfloat16* __restrict__ olo) {
    int gtid = blockIdx.x * blockDim.x + threadIdx.x;
    int node = gtid >> 5;
    int lane = threadIdx.x & 31;
    if (node >= N_NODES) return;

    float4 qv = ((const float4*)q)[node * 32 + lane];
    float z0 = 0.0f, z1 = 0.0f;
    float4 accA = make_float4(0.f, 0.f, 0.f, 0.f);
    float4 accB = make_float4(0.f, 0.f, 0.f, 0.f);

    int e0 = rp[node];
    int e1 = rp[node + 1];
    int nb = (e1 - e0) >> 2;  // number of full 4-edge batches
    int e = e0;

    // double-buffered pipeline over batches: load next while computing current
    uint2 ka0, ka1, ka2, ka3, va0, va1, va2, va3;
    uint2 kb0, kb1, kb2, kb3, vb0, vb1, vb2, vb3;

    if (nb > 0) ATTN_LOAD(ka0, ka1, ka2, ka3, va0, va1, va2, va3, e);
    int b = 0;
    while (b < nb) {
        // buffer A holds batch b; prefetch b+1 into B
        if (b + 1 < nb) ATTN_LOAD(kb0, kb1, kb2, kb3, vb0, vb1, vb2, vb3, e + 4);
        ATTN_COMPUTE(ka0, ka1, ka2, ka3, va0, va1, va2, va3);
        e += 4;
        b++;
        if (b >= nb) break;
        // buffer B holds batch b; prefetch b+1 into A
        if (b + 1 < nb) ATTN_LOAD(ka0, ka1, ka2, ka3, va0, va1, va2, va3, e + 4);
        ATTN_COMPUTE(kb0, kb1, kb2, kb3, vb0, vb1, vb2, vb3);
        e += 4;
        b++;
    }
    // scalar tail
    for (; e < e1; e++) {
        int src = __ldg(esrc + e);
        const __nv_bfloat16* bp = kv + (size_t)src * 256 + lane * 4;
        uint2 kr = *(const uint2*)bp;
        uint2 vr = *(const uint2*)(bp + 128);
        float sc = edge_score(qv, bf2f(kr.x), bf2f(kr.y));
        float2 v0 = bf2f(vr.x);
        float2 v1 = bf2f(vr.y);
        z0 += sc;
        accA.x += sc * v0.x;
        accA.y += sc * v0.y;
        accA.z += sc * v1.x;
        accA.w += sc * v1.y;
    }

    float z = z0 + z1;
    float inv = 1.0f / (z + 1e-6f);
    float xs[4] = {(accA.x + accB.x) * inv, (accA.y + accB.y) * inv,
                   (accA.z + accB.z) * inv, (accA.w + accB.w) * inv};
    uint2 phi, plo;
    pack_hilo4(xs, phi, plo);
    size_t obase = (size_t)node * HID + lane * 4;
    *(uint2*)&ohi[obase] = phi;
    *(uint2*)&olo[obase] = plo;
}

// ============================================================================
// Shared GEMM mainloop (BM=128, BN=128, BK=32, double-buffered cp.async)
// All GEMMs 3-term: 2-term drops a COHERENT ~2^-9 perturbation that does NOT
// attenuate downstream (verified R11/R12 failures).
// ============================================================================
#define GEMM_SMEM 81920
#define STG_H 20480  // halves per stage

#define GEMM_LOAD_STAGE(k0, base)                                                   \
    {                                                                               \
        _Pragma("unroll") for (int j = 0; j < 2; j++) {                             \
            int r = r_ld + j * 64;                                                  \
            int gm = m0 + r;                                                        \
            int gmc = (gm < M) ? gm : 0;                                            \
            int sza = (gm < M) ? 16 : 0;                                            \
            unsigned dA = smb + (unsigned)((base) + r * 40 + cc_ld) * 2;            \
            cp16(dA, Ahi + (size_t)gmc * K + (k0) + cc_ld, sza);                    \
            cp16(dA + 10240, Alo + (size_t)gmc * K + (k0) + cc_ld, sza);            \
            int gn = n0 + r;                                                        \
            int gnc = (gn < N) ? gn : 0;                                            \
            int szb = (gn < N) ? 16 : 0;                                            \
            unsigned dB = smb + (unsigned)((base) + 10240 + r * 40 + cc_ld) * 2;    \
            cp16(dB, Bhi + (size_t)gnc * K + (k0) + cc_ld, szb);                    \
            cp16(dB + 10240, Blo + (size_t)gnc * K + (k0) + cc_ld, szb);            \
        }                                                                           \
        asm volatile("cp.async.commit_group;");                                     \
    }

#define GEMM_COMPUTE_STAGE(base)                                                    \
    {                                                                               \
        _Pragma("unroll") for (int kk = 0; kk < 32; kk += 16) {                     \
            unsigned ah[2][4], al[2][4];                                            \
            _Pragma("unroll") for (int mt = 0; mt < 2; mt++) {                      \
                int row = wm0 + mt * 16 + a_row;                                    \
                ldmx4(ah[mt], sm + (base) + row * 40 + kk + a_kc);                  \
                ldmx4(al[mt], sm + (base) + 5120 + row * 40 + kk + a_kc);           \
            }                                                                       \
            _Pragma("unroll") for (int p4 = 0; p4 < 4; p4++) {                      \
                unsigned bh[4], bl[4];                                              \
                int row = wn0 + p4 * 16 + b_row;                                    \
                ldmx4(bh, sm + (base) + 10240 + row * 40 + kk + b_kc);              \
                ldmx4(bl, sm + (base) + 15360 + row * 40 + kk + b_kc);              \
                _Pragma("unroll") for (int sub = 0; sub < 2; sub++) {               \
                    int nt = p4 * 2 + sub;                                          \
                    unsigned b0 = bh[sub * 2], b1 = bh[sub * 2 + 1];                \
                    unsigned c0 = bl[sub * 2], c1 = bl[sub * 2 + 1];                \
                    _Pragma("unroll") for (int mt = 0; mt < 2; mt++) {              \
                        mma16816(acc[mt][nt], ah[mt], b0, b1);                      \
                        mma16816(acc[mt][nt], ah[mt], c0, c1);                      \
                        mma16816(acc[mt][nt], al[mt], b0, b1);                      \
                    }                                                               \
                }                                                                   \
            }                                                                       \
        }                                                                           \
    }

#define GEMM_MAINLOOP()                                                             \
    GEMM_LOAD_STAGE(0, 0);                                                          \
    int buf = 0;                                                                    \
    int nIter = K >> 5;                                                             \
    for (int it = 0; it < nIter; it++) {                                            \
        if (it + 1 < nIter) {                                                       \
            GEMM_LOAD_STAGE((it + 1) * 32, (buf ^ 1) * STG_H);                      \
            asm volatile("cp.async.wait_group 1;");                                 \
        } else {                                                                    \
            asm volatile("cp.async.wait_group 0;");                                 \
        }                                                                           \
        __syncthreads();                                                            \
        GEMM_COMPUTE_STAGE(buf * STG_H);                                            \
        __syncthreads();                                                            \
        buf ^= 1;                                                                   \
    }

#define GEMM_PREAMBLE()                                                             \
    extern __shared__ __nv_bfloat16 sm[];                                           \
    unsigned smb = (unsigned)__cvta_generic_to_shared(sm);                          \
    int t = threadIdx.x, lane = t & 31, w = t >> 5;                                 \
    int m0 = blockIdx.x * 128, n0 = blockIdx.y * 128;                               \
    int wm0 = (w >> 1) * 32;                                                        \
    int wn0 = (w & 1) * 64;                                                         \
    float acc[2][8][4];                                                             \
    _Pragma("unroll") for (int mt = 0; mt < 2; mt++)                                \
        _Pragma("unroll") for (int nt = 0; nt < 8; nt++)                            \
            _Pragma("unroll") for (int i = 0; i < 4; i++) acc[mt][nt][i] = 0.f;     \
    int grp = lane >> 3, lrow = lane & 7;                                           \
    int a_row = lrow + (grp & 1) * 8;                                               \
    int a_kc = (grp >> 1) * 8;                                                      \
    int b_row = lrow + (grp >> 1) * 8;                                              \
    int b_kc = (grp & 1) * 8;                                                       \
    int r_ld = t >> 2;                                                              \
    int cc_ld = (t & 3) * 8;

// ---------------- plain tc GEMM (bias/relu; f32 and/or hi-lo; optional QKV-split out) ----------------
__global__ void __launch_bounds__(256, 2) gemm_tc2_kernel(
    const __nv_bfloat16* __restrict__ Ahi, const __nv_bfloat16* __restrict__ Alo,
    const __nv_bfloat16* __restrict__ Bhi, const __nv_bfloat16* __restrict__ Blo,
    const float* __restrict__ bias, float* __restrict__ C,
    __nv_bfloat16* __restrict__ Chi, __nv_bfloat16* __restrict__ Clo,
    int M, int K, int N, int relu,
    float* __restrict__ Q, __nv_bfloat16* __restrict__ KV) {
    GEMM_PREAMBLE();
    GEMM_MAINLOOP();

    int rr = lane >> 2, c2 = (lane & 3) * 2;
    if (KV) {
#pragma unroll
        for (int mt = 0; mt < 2; mt++) {
#pragma unroll
            for (int nt = 0; nt < 8; nt++) {
                int n = n0 + wn0 + nt * 8 + c2;
#pragma unroll
                for (int half = 0; half < 2; half++) {
                    int m = m0 + wm0 + mt * 16 + rr + half * 8;
                    if (m >= M) continue;
                    float v0 = acc[mt][nt][half * 2];
                    float v1 = acc[mt][nt][half * 2 + 1];
                    if (n < 128) {
                        *(float2*)&Q[(size_t)m * 128 + n] = make_float2(v0, v1);
                    } else {
                        __nv_bfloat162 p;
                        p.x = __float2bfloat16(v0);
                        p.y = __float2bfloat16(v1);
                        *(__nv_bfloat162*)&KV[(size_t)m * 256 + (n - 128)] = p;
                    }
                }
            }
        }
        return;
    }
#pragma unroll
    for (int mt = 0; mt < 2; mt++) {
#pragma unroll
        for (int nt = 0; nt < 8; nt++) {
            int n = n0 + wn0 + nt * 8 + c2;
            if (n >= N) continue;
            float bx = 0.f, by = 0.f;
            if (bias) { bx = bias[n]; by = bias[n + 1]; }
#pragma unroll
            for (int half = 0; half < 2; half++) {
                int m = m0 + wm0 + mt * 16 + rr + half * 8;
                if (m >= M) continue;
                float v0 = acc[mt][nt][half * 2] + bx;
                float v1 = acc[mt][nt][half * 2 + 1] + by;
                if (relu) { v0 = fmaxf(v0, 0.f); v1 = fmaxf(v1, 0.f); }
                if (C) *(float2*)&C[(size_t)m * N + n] = make_float2(v0, v1);
                if (Chi) {
                    __nv_bfloat16 h0, l0, h1, l1;
                    split_bf16(v0, h0, l0);
                    split_bf16(v1, h1, l1);
                    __nv_bfloat162 ph, pl;
                    ph.x = h0; ph.y = h1;
                    pl.x = l0; pl.y = l1;
                    *(__nv_bfloat162*)&Chi[(size_t)m * N + n] = ph;
                    *(__nv_bfloat162*)&Clo[(size_t)m * N + n] = pl;
                }
            }
        }
    }
}

// ---------------- fused GEMM + bias + residual(hi/lo) + LayerNorm (N=128) ----------------
__global__ void __launch_bounds__(256, 2) gemm_ln_kernel(
    const __nv_bfloat16* __restrict__ Ahi, const __nv_bfloat16* __restrict__ Alo,
    const __nv_bfloat16* __restrict__ Bhi, const __nv_bfloat16* __restrict__ Blo,
    const float* __restrict__ bias,
    const __nv_bfloat16* __restrict__ resHi, const __nv_bfloat16* __restrict__ resLo,
    const float* __restrict__ lng, const float* __restrict__ lnb,
    __nv_bfloat16* __restrict__ outHi, __nv_bfloat16* __restrict__ outLo, int M, int K) {
    const int N = 128;
    GEMM_PREAMBLE();
    GEMM_MAINLOOP();

    __shared__ float red[128][4];
    int rr = lane >> 2, c2 = (lane & 3) * 2;

    float sums[2][2] = {{0.f, 0.f}, {0.f, 0.f}};
    float sqs[2][2] = {{0.f, 0.f}, {0.f, 0.f}};
#pragma unroll
    for (int mt = 0; mt < 2; mt++) {
#pragma unroll
        for (int nt = 0; nt < 8; nt++) {
            int n = wn0 + nt * 8 + c2;
            float bx = bias[n], by = bias[n + 1];
#pragma unroll
            for (int half = 0; half < 2; half++) {
                int m = m0 + wm0 + mt * 16 + rr + half * 8;
                int mc = (m < M) ? m : 0;
                float2 rh = __bfloat1622float2(*(const __nv_bfloat162*)&resHi[(size_t)mc * N + n]);
                float2 rl = __bfloat1622float2(*(const __nv_bfloat162*)&resLo[(size_t)mc * N + n]);
                float v0 = acc[mt][nt][half * 2] + bx + rh.x + rl.x;
                float v1 = acc[mt][nt][half * 2 + 1] + by + rh.y + rl.y;
                acc[mt][nt][half * 2] = v0;
                acc[mt][nt][half * 2 + 1] = v1;
                sums[mt][half] += v0 + v1;
                sqs[mt][half] += v0 * v0 + v1 * v1;
            }
        }
    }
#pragma unroll
    for (int mt = 0; mt < 2; mt++)
#pragma unroll
        for (int half = 0; half < 2; half++) {
            float s = sums[mt][half], q = sqs[mt][half];
            s += __shfl_xor_sync(0xffffffffu, s, 1);
            s += __shfl_xor_sync(0xffffffffu, s, 2);
            q += __shfl_xor_sync(0xffffffffu, q, 1);
            q += __shfl_xor_sync(0xffffffffu, q, 2);
            sums[mt][half] = s;
            sqs[mt][half] = q;
        }
    if ((lane & 3) == 0) {
#pragma unroll
        for (int mt = 0; mt < 2; mt++)
#pragma unroll
            for (int half = 0; half < 2; half++) {
                int row = wm0 + mt * 16 + rr + half * 8;
                red[row][(w & 1) * 2] = sums[mt][half];
                red[row][(w & 1) * 2 + 1] = sqs[mt][half];
            }
    }
    __syncthreads();

#pragma unroll
    for (int mt = 0; mt < 2; mt++) {
#pragma unroll
        for (int half = 0; half < 2; half++) {
            int row = wm0 + mt * 16 + rr + half * 8;
            float s = red[row][0] + red[row][2];
            float q = red[row][1] + red[row][3];
            float mu = s * (1.0f / 128.0f);
            float var = q * (1.0f / 128.0f) - mu * mu;
            float rstd = rsqrtf(var + 1e-5f);
            int m = m0 + row;
            if (m >= M) continue;
#pragma unroll
            for (int nt = 0; nt < 8; nt++) {
                int n = wn0 + nt * 8 + c2;
                float gx = lng[n], gy = lng[n + 1];
                float bx = lnb[n], by = lnb[n + 1];
                float v0 = (acc[mt][nt][half * 2] - mu) * rstd * gx + bx;
                float v1 = (acc[mt][nt][half * 2 + 1] - mu) * rstd * gy + by;
                __nv_bfloat16 h0, l0, h1, l1;
                split_bf16(v0, h0, l0);
                split_bf16(v1, h1, l1);
                __nv_bfloat162 ph, pl;
                ph.x = h0; ph.y = h1;
                pl.x = l0; pl.y = l1;
                *(__nv_bfloat162*)&outHi[(size_t)m * N + n] = ph;
                *(__nv_bfloat162*)&outLo[(size_t)m * N + n] = pl;
            }
        }
    }
}

static void gemm_tc(const __nv_bfloat16* Ahi, const __nv_bfloat16* Alo,
                    const __nv_bfloat16* Bhi, const __nv_bfloat16* Blo,
                    const float* bias, float* C, __nv_bfloat16* Chi, __nv_bfloat16* Clo,
                    int M, int K, int N, int relu, float* Q = nullptr,
                    __nv_bfloat16* KV = nullptr) {
    cudaFuncSetAttribute(gemm_tc2_kernel, cudaFuncAttributeMaxDynamicSharedMemorySize, GEMM_SMEM);
    dim3 grid((M + 127) / 128, (N + 127) / 128);
    gemm_tc2_kernel<<<grid, 256, GEMM_SMEM>>>(Ahi, Alo, Bhi, Blo, bias, C, Chi, Clo,
                                              M, K, N, relu, Q, KV);
}

static void gemm_ln(const __nv_bfloat16* Ahi, const __nv_bfloat16* Alo,
                    const __nv_bfloat16* Bhi, const __nv_bfloat16* Blo,
                    const float* bias, const __nv_bfloat16* resHi, const __nv_bfloat16* resLo,
                    const float* lng, const float* lnb,
                    __nv_bfloat16* outHi, __nv_bfloat16* outLo, int M, int K) {
    cudaFuncSetAttribute(gemm_ln_kernel, cudaFuncAttributeMaxDynamicSharedMemorySize, GEMM_SMEM);
    dim3 grid((M + 127) / 128, 1);
    gemm_ln_kernel<<<grid, 256, GEMM_SMEM>>>(Ahi, Alo, Bhi, Blo, bias, resHi, resLo,
                                             lng, lnb, outHi, outLo, M, K);
}

// ---------------- SIMT fallback GEMM (small N readout tail) ----------------
#define BMg 64
#define BNg 64
#define BKg 16
__global__ void __launch_bounds__(256) gemm_kernel(
    const float* __restrict__ A, const float* __restrict__ B,
    const float* __restrict__ bias, float* __restrict__ C, int M, int K, int N, int relu) {
    __shared__ float As[BKg][BMg + 1];
    __shared__ float Bs[BKg][BNg];

    int t = threadIdx.x;
    int m0 = blockIdx.x * BMg;
    int n0 = blockIdx.y * BNg;
    int ty = t >> 4;
    int tx = t & 15;

    int arow = t >> 2;
    int akc = (t & 3) * 4;
    int brow = t >> 4;
    int bnc = (t & 15) * 4;

    unsigned long long acc[4][2];
#pragma unroll
    for (int i = 0; i < 4; i++) { acc[i][0] = 0ull; acc[i][1] = 0ull; }

    for (int k0 = 0; k0 < K; k0 += BKg) {
        float4 av = make_float4(0.f, 0.f, 0.f, 0.f);
        if (m0 + arow < M) av = *(const float4*)&A[(size_t)(m0 + arow) * K + k0 + akc];
        As[akc + 0][arow] = av.x;
        As[akc + 1][arow] = av.y;
        As[akc + 2][arow] = av.z;
        As[akc + 3][arow] = av.w;

        float4 bv = make_float4(0.f, 0.f, 0.f, 0.f);
        if (n0 + bnc < N) bv = *(const float4*)&B[(size_t)(k0 + brow) * N + n0 + bnc];
        *(float4*)&Bs[brow][bnc] = bv;

        __syncthreads();
#pragma unroll
        for (int kk = 0; kk < BKg; kk++) {
            unsigned long long b0 = *(const unsigned long long*)&Bs[kk][tx * 4];
            unsigned long long b1 = *(const unsigned long long*)&Bs[kk][tx * 4 + 2];
            const float* ap = &As[kk][ty * 4];
#pragma unroll
            for (int i = 0; i < 4; i++) {
                unsigned long long aa = pack2(ap[i]);
                fma2(acc[i][0], aa, b0, acc[i][0]);
                fma2(acc[i][1], aa, b1, acc[i][1]);
            }
        }
        __syncthreads();
    }

#pragma unroll
    for (int i = 0; i < 4; i++) {
        int m = m0 + ty * 4 + i;
        if (m >= M) continue;
        float vals[4];
        unpack2(acc[i][0], vals[0], vals[1]);
        unpack2(acc[i][1], vals[2], vals[3]);
#pragma unroll
        for (int j = 0; j < 4; j++) {
            int n = n0 + tx * 4 + j;
            if (n >= N) continue;
            float val = vals[j];
            if (bias) val += bias[n];
            if (relu) val = fmaxf(val, 0.0f);
            C[(size_t)m * N + n] = val;
        }
    }
}

static void gemm_simt(const float* A, const float* B, const float* bias,
                      float* C, int M, int K, int N, int relu) {
    dim3 grid((M + BMg - 1) / BMg, (N + BNg - 1) / BNg);
    gemm_kernel<<<grid, 256>>>(A, B, bias, C, M, K, N, relu);
}

// ---------------- driver ----------------
extern "C" void kernel_launch(void* const* d_in, const int* in_sizes, int n_in,
                              void* d_out, int out_size) {
    const int* feat = (const int*)d_in[0];
    const int* esrc = (const int*)d_in[1];
    const int* edst = (const int*)d_in[2];
    const float* emb = (const float*)d_in[3];
    const float* Wq = (const float*)d_in[4];
    const float* Wk = (const float*)d_in[5];
    const float* Wv = (const float*)d_in[6];
    const float* Wo = (const float*)d_in[7];
    const float* bo = (const float*)d_in[8];
    const float* ln1_g = (const float*)d_in[9];
    const float* ln1_b = (const float*)d_in[10];
    const float* W1 = (const float*)d_in[11];
    const float* b1 = (const float*)d_in[12];
    const float* W2 = (const float*)d_in[13];
    const float* b2 = (const float*)d_in[14];
    const float* ln2_g = (const float*)d_in[15];
    const float* ln2_b = (const float*)d_in[16];
    const float* mW0 = (const float*)d_in[17];
    const float* mb0 = (const float*)d_in[18];
    const float* mW1 = (const float*)d_in[19];
    const float* mb1 = (const float*)d_in[20];
    const float* mW2 = (const float*)d_in[21];
    const float* mb2 = (const float*)d_in[22];
    float* out = (float*)d_out;

    float *q, *t0, *t1;
    int* rp;
    __nv_bfloat16 *kv;
    __nv_bfloat16 *h_hi, *h_lo, *attn_hi, *attn_lo, *mid_hi, *mid_lo;
    __nv_bfloat16 *wqkv_hi, *wqkv_lo, *wo_hi, *wo_lo, *w1_hi, *w1_lo, *w2_hi, *w2_lo, *m0_hi, *m0_lo;
    cudaGetSymbolAddress((void**)&q, g_q);
    cudaGetSymbolAddress((void**)&kv, g_kv);
    cudaGetSymbolAddress((void**)&t0, g_t0);
    cudaGetSymbolAddress((void**)&t1, g_t1);
    cudaGetSymbolAddress((void**)&rp, g_rowptr);
    cudaGetSymbolAddress((void**)&h_hi, g_h_hi);
    cudaGetSymbolAddress((void**)&h_lo, g_h_lo);
    cudaGetSymbolAddress((void**)&attn_hi, g_attn_hi);
    cudaGetSymbolAddress((void**)&attn_lo, g_attn_lo);
    cudaGetSymbolAddress((void**)&mid_hi, g_mid_hi);
    cudaGetSymbolAddress((void**)&mid_lo, g_mid_lo);
    cudaGetSymbolAddress((void**)&wqkv_hi, g_wqkv_hi);
    cudaGetSymbolAddress((void**)&wqkv_lo, g_wqkv_lo);
    cudaGetSymbolAddress((void**)&wo_hi, g_wo_hi);
    cudaGetSymbolAddress((void**)&wo_lo, g_wo_lo);
    cudaGetSymbolAddress((void**)&w1_hi, g_w1_hi);
    cudaGetSymbolAddress((void**)&w1_lo, g_w1_lo);
    cudaGetSymbolAddress((void**)&w2_hi, g_w2_hi);
    cudaGetSymbolAddress((void**)&w2_lo, g_w2_lo);
    cudaGetSymbolAddress((void**)&m0_hi, g_m0_hi);
    cudaGetSymbolAddress((void**)&m0_lo, g_m0_lo);

    // launch 1: square weights + readout m0
    {
        int tot = 4 * SQ_TOT + HID * 64;
        splitw_a_kernel<<<(tot + 255) / 256, 256>>>(Wq, Wk, Wv, Wo, mW0, wqkv_hi, wqkv_lo,
                                                    wo_hi, wo_lo, m0_hi, m0_lo);
    }
    // launch 2: FFN weights
    {
        int tot = 2 * RT_TOT;
        splitw_b_kernel<<<(tot + 255) / 256, 256>>>(W1, W2, w1_hi, w1_lo, w2_hi, w2_lo);
    }

    int warp_threads = N_NODES * 32;
    int wblocks = (warp_threads + 255) / 256;

    // launch 3
    rowptr_kernel<<<(N_NODES + 1 + 255) / 256, 256>>>(edst, rp);
    // launch 4
    embed_kernel<<<wblocks, 256>>>(feat, emb, h_hi, h_lo);

    for (int l = 0; l < N_LAYERS; l++) {
        const __nv_bfloat16* wqkvh = wqkv_hi + (size_t)l * 3 * HID * HID;
        const __nv_bfloat16* wqkvl = wqkv_lo + (size_t)l * 3 * HID * HID;
        const __nv_bfloat16* woh = wo_hi + (size_t)l * HID * HID;
        const __nv_bfloat16* wol = wo_lo + (size_t)l * HID * HID;
        const __nv_bfloat16* w1h = w1_hi + (size_t)l * 2 * HID * HID;
        const __nv_bfloat16* w1l = w1_lo + (size_t)l * 2 * HID * HID;
        const __nv_bfloat16* w2h = w2_hi + (size_t)l * HID * 2 * HID;
        const __nv_bfloat16* w2l = w2_lo + (size_t)l * HID * 2 * HID;

        // fused QKV -> q fp32 + kv bf16
        gemm_tc(h_hi, h_lo, wqkvh, wqkvl, nullptr, nullptr, nullptr, nullptr,
                N_NODES, HID, 3 * HID, 0, q, kv);

        attn_kernel<<<wblocks, 256>>>(q, kv, rp, esrc, attn_hi, attn_lo);

        // h = LN1(h + attn @ Wo + bo)
        gemm_ln(attn_hi, attn_lo, woh, wol, bo + l * HID, h_hi, h_lo,
                ln1_g + l * HID, ln1_b + l * HID, h_hi, h_lo, N_NODES, HID);
        // mid = relu(h @ W1 + b1)
        gemm_tc(h_hi, h_lo, w1h, w1l, b1 + l * 2 * HID, nullptr, mid_hi, mid_lo,
                N_NODES, HID, 2 * HID, 1);
        // h = LN2(h + mid @ W2 + b2)
        gemm_ln(mid_hi, mid_lo, w2h, w2l, b2 + l * HID, h_hi, h_lo,
                ln2_g + l * HID, ln2_b + l * HID, h_hi, h_lo, N_NODES, 2 * HID);
    }

    // readout: 128 -> 64 (tc) -> 32 -> 16 (SIMT)
    gemm_tc(h_hi, h_lo, m0_hi, m0_lo, mb0, t0, nullptr, nullptr, N_NODES, HID, 64, 1);
    gemm_simt(t0, mW1, mb1, t1, N_NODES, 64, 32, 1);
    gemm_simt(t1, mW2, mb2, out, N_NODES, 32, N_CLASSES, 0);
}

// round 15
// speedup vs baseline: 1.0690x; 1.0690x over previous
#include <cuda_runtime.h>
#include <cuda_bf16.h>
#include <math.h>

#define N_NODES 100000
#define N_EDGES 1600000
#define HID 128
#define HEADS 8
#define N_LAYERS 4
#define IN_DIM 32
#define N_CLASSES 16

// ---------------- scratch (device globals; no allocation allowed) ----------------
__device__ float g_q[N_NODES * HID];
__device__ __nv_bfloat16 g_kv[N_NODES * 2 * HID];   // k then v, bf16, per node
__device__ float g_t0[N_NODES * 64];
__device__ float g_t1[N_NODES * 32];
__device__ int g_rowptr[N_NODES + 1];

// bf16 hi/lo activation buffers (hi+lo reconstructs ~fp32)
__device__ __nv_bfloat16 g_h_hi[N_NODES * HID];
__device__ __nv_bfloat16 g_h_lo[N_NODES * HID];
__device__ __nv_bfloat16 g_attn_hi[N_NODES * HID];
__device__ __nv_bfloat16 g_attn_lo[N_NODES * HID];
__device__ __nv_bfloat16 g_mid_hi[N_NODES * 2 * HID];
__device__ __nv_bfloat16 g_mid_lo[N_NODES * 2 * HID];

// bf16 hi/lo transposed weights (B^T layout: [rows=N][cols=K])
__device__ __nv_bfloat16 g_wqkv_hi[N_LAYERS * 3 * HID * HID];
__device__ __nv_bfloat16 g_wqkv_lo[N_LAYERS * 3 * HID * HID];
__device__ __nv_bfloat16 g_wo_hi[N_LAYERS * HID * HID];
__device__ __nv_bfloat16 g_wo_lo[N_LAYERS * HID * HID];
__device__ __nv_bfloat16 g_w1_hi[N_LAYERS * 2 * HID * HID];
__device__ __nv_bfloat16 g_w1_lo[N_LAYERS * 2 * HID * HID];
__device__ __nv_bfloat16 g_w2_hi[N_LAYERS * HID * 2 * HID];
__device__ __nv_bfloat16 g_w2_lo[N_LAYERS * HID * 2 * HID];
__device__ __nv_bfloat16 g_m0_hi[64 * HID];
__device__ __nv_bfloat16 g_m0_lo[64 * HID];

// ---------------- helpers ----------------
__device__ __forceinline__ void split_bf16(float x, __nv_bfloat16& hi, __nv_bfloat16& lo) {
    hi = __float2bfloat16(x);
    lo = __float2bfloat16(x - __bfloat162float(hi));
}
__device__ __forceinline__ void ldmx4(unsigned r[4], const void* p) {
    unsigned addr = (unsigned)__cvta_generic_to_shared(p);
    asm volatile("ldmatrix.sync.aligned.m8n8.x4.shared.b16 {%0,%1,%2,%3}, [%4];"
                 : "=r"(r[0]), "=r"(r[1]), "=r"(r[2]), "=r"(r[3])
                 : "r"(addr));
}
__device__ __forceinline__ void mma16816(float d[4], const unsigned a[4],
                                         unsigned b0, unsigned b1) {
    asm volatile(
        "mma.sync.aligned.m16n8k16.row.col.f32.bf16.bf16.f32 "
        "{%0,%1,%2,%3},{%4,%5,%6,%7},{%8,%9},{%0,%1,%2,%3};"
        : "+f"(d[0]), "+f"(d[1]), "+f"(d[2]), "+f"(d[3])
        : "r"(a[0]), "r"(a[1]), "r"(a[2]), "r"(a[3]), "r"(b0), "r"(b1));
}
__device__ __forceinline__ void cp16(unsigned dst, const void* src, int sz) {
    asm volatile("cp.async.cg.shared.global [%0], [%1], 16, %2;"
                 :: "r"(dst), "l"(src), "r"(sz));
}
__device__ __forceinline__ void fma2(unsigned long long& d, unsigned long long a,
                                     unsigned long long b, unsigned long long c) {
    asm("fma.rn.f32x2 %0, %1, %2, %3;" : "=l"(d) : "l"(a), "l"(b), "l"(c));
}
__device__ __forceinline__ unsigned long long pack2(float x) {
    unsigned long long d;
    unsigned u = __float_as_uint(x);
    asm("mov.b64 %0, {%1, %2};" : "=l"(d) : "r"(u), "r"(u));
    return d;
}
__device__ __forceinline__ void unpack2(unsigned long long v, float& lo, float& hi) {
    unsigned a, b;
    asm("mov.b64 {%0, %1}, %2;" : "=r"(a), "=r"(b) : "l"(v));
    lo = __uint_as_float(a);
    hi = __uint_as_float(b);
}
// pack 4 floats into hi-uint2 and lo-uint2 (bf16x2 pairs)
__device__ __forceinline__ void pack_hilo4(const float* xs, uint2& phi, uint2& plo) {
    __nv_bfloat16 h[4], l[4];
#pragma unroll
    for (int i = 0; i < 4; i++) split_bf16(xs[i], h[i], l[i]);
    __nv_bfloat162 h01, h23, l01, l23;
    h01.x = h[0]; h01.y = h[1];
    h23.x = h[2]; h23.y = h[3];
    l01.x = l[0]; l01.y = l[1];
    l23.x = l[2]; l23.y = l[3];
    phi.x = *(unsigned*)&h01;
    phi.y = *(unsigned*)&h23;
    plo.x = *(unsigned*)&l01;
    plo.y = *(unsigned*)&l23;
}
__device__ __forceinline__ float2 bf2f(unsigned u) {
    return __bfloat1622float2(*(__nv_bfloat162*)&u);
}

// ---------------- weight split+transpose (consolidated into 2 launches) ----------------
__device__ __forceinline__ void splitw_store(const float* W, __nv_bfloat16* hi,
                                             __nv_bfloat16* lo, int idx, int K, int N,
                                             int lsRows, int rowOff) {
    int l = idx / (K * N);
    int rem = idx - l * K * N;
    int k = rem / N;
    int n = rem - k * N;
    float x = W[idx];
    __nv_bfloat16 h, lw;
    split_bf16(x, h, lw);
    size_t d = ((size_t)(l * lsRows + rowOff + n)) * K + k;
    hi[d] = h;
    lo[d] = lw;
}

// kernel A: Wq, Wk, Wv, Wo, mW0
#define SQ_TOT (N_LAYERS * HID * HID)
__global__ void splitw_a_kernel(const float* __restrict__ Wq, const float* __restrict__ Wk,
                                const float* __restrict__ Wv, const float* __restrict__ Wo,
                                const float* __restrict__ mW0,
                                __nv_bfloat16* __restrict__ qkv_hi, __nv_bfloat16* __restrict__ qkv_lo,
                                __nv_bfloat16* __restrict__ wo_hi, __nv_bfloat16* __restrict__ wo_lo,
                                __nv_bfloat16* __restrict__ m0_hi, __nv_bfloat16* __restrict__ m0_lo) {
    int idx = blockIdx.x * blockDim.x + threadIdx.x;
    if (idx < SQ_TOT) {
        splitw_store(Wq, qkv_hi, qkv_lo, idx, HID, HID, 3 * HID, 0);
        return;
    }
    idx -= SQ_TOT;
    if (idx < SQ_TOT) {
        splitw_store(Wk, qkv_hi, qkv_lo, idx, HID, HID, 3 * HID, HID);
        return;
    }
    idx -= SQ_TOT;
    if (idx < SQ_TOT) {
        splitw_store(Wv, qkv_hi, qkv_lo, idx, HID, HID, 3 * HID, 2 * HID);
        return;
    }
    idx -= SQ_TOT;
    if (idx < SQ_TOT) {
        splitw_store(Wo, wo_hi, wo_lo, idx, HID, HID, HID, 0);
        return;
    }
    idx -= SQ_TOT;
    if (idx < HID * 64) {
        splitw_store(mW0, m0_hi, m0_lo, idx, HID, 64, 64, 0);
    }
}

// kernel B: W1, W2
#define RT_TOT (N_LAYERS * HID * 2 * HID)
__global__ void splitw_b_kernel(const float* __restrict__ W1, const float* __restrict__ W2,
                                __nv_bfloat16* __restrict__ w1_hi, __nv_bfloat16* __restrict__ w1_lo,
                                __nv_bfloat16* __restrict__ w2_hi, __nv_bfloat16* __restrict__ w2_lo) {
    int idx = blockIdx.x * blockDim.x + threadIdx.x;
    if (idx < RT_TOT) {
        splitw_store(W1, w1_hi, w1_lo, idx, HID, 2 * HID, 2 * HID, 0);
        return;
    }
    idx -= RT_TOT;
    if (idx < RT_TOT) {
        splitw_store(W2, w2_hi, w2_lo, idx, 2 * HID, HID, HID, 0);
    }
}

// ---------------- embedding gather (hi/lo, vectorized stores) ----------------
__global__ void embed_kernel(const int* __restrict__ feat, const float* __restrict__ emb,
                             __nv_bfloat16* __restrict__ hhi, __nv_bfloat16* __restrict__ hlo) {
    int idx = blockIdx.x * blockDim.x + threadIdx.x;
    if (idx >= N_NODES * 32) return;
    int n = idx >> 5, c4 = idx & 31;
    int f = feat[n];
    float4 v = ((const float4*)emb)[f * 32 + c4];
    float xs[4] = {v.x, v.y, v.z, v.w};
    uint2 phi, plo;
    pack_hilo4(xs, phi, plo);
    size_t base = (size_t)n * HID + c4 * 4;
    *(uint2*)&hhi[base] = phi;
    *(uint2*)&hlo[base] = plo;
}

// ---------------- CSR row pointers from sorted edge_dst ----------------
__global__ void rowptr_kernel(const int* __restrict__ dst, int* __restrict__ rp) {
    int n = blockIdx.x * blockDim.x + threadIdx.x;
    if (n > N_NODES) return;
    if (n == N_NODES) { rp[n] = N_EDGES; return; }
    int lo = 0, hi = N_EDGES;
    while (lo < hi) {
        int mid = (lo + hi) >> 1;
        if (dst[mid] < n) lo = mid + 1; else hi = mid;
    }
    rp[n] = lo;
}

// ---------------- per-node attention: 4-edge unrolled straight-line (R13 form) ----------------
__device__ __forceinline__ float edge_score(float4 qv, float2 k0, float2 k1) {
    float s = k0.x * qv.x + k0.y * qv.y + k1.x * qv.z + k1.y * qv.w;
    s += __shfl_xor_sync(0xffffffffu, s, 1);
    s += __shfl_xor_sync(0xffffffffu, s, 2);
    s *= 0.25f;
    s = fminf(fmaxf(s, -5.0f), 5.0f);
    return __expf(s);
}

__global__ void attn_kernel(const float* __restrict__ q, const __nv_bfloat16* __restrict__ kv,
                            const int* __restrict__ rp, const int* __restrict__ esrc,
                            __nv_bfloat16* __restrict__ ohi, __nv_bfloat16* __restrict__ olo) {
    int gtid = blockIdx.x * blockDim.x + threadIdx.x;
    int node = gtid >> 5;
    int lane = threadIdx.x & 31;
    if (node >= N_NODES) return;

    float4 qv = ((const float4*)q)[node * 32 + lane];
    float z0 = 0.0f, z1 = 0.0f;
    float4 accA = make_float4(0.f, 0.f, 0.f, 0.f);
    float4 accB = make_float4(0.f, 0.f, 0.f, 0.f);

    int e0 = rp[node];
    int e1 = rp[node + 1];
    int e = e0;

    for (; e + 4 <= e1; e += 4) {
        int s0 = __ldg(esrc + e);
        int s1 = __ldg(esrc + e + 1);
        int s2 = __ldg(esrc + e + 2);
        int s3 = __ldg(esrc + e + 3);
        const __nv_bfloat16* b0 = kv + (size_t)s0 * 256 + lane * 4;
        const __nv_bfloat16* b1 = kv + (size_t)s1 * 256 + lane * 4;
        const __nv_bfloat16* b2 = kv + (size_t)s2 * 256 + lane * 4;
        const __nv_bfloat16* b3 = kv + (size_t)s3 * 256 + lane * 4;
        // ptxas front-batches these 8 gathers (MLP=8)
        uint2 kr0 = *(const uint2*)b0;
        uint2 kr1 = *(const uint2*)b1;
        uint2 kr2 = *(const uint2*)b2;
        uint2 kr3 = *(const uint2*)b3;
        uint2 vr0 = *(const uint2*)(b0 + 128);
        uint2 vr1 = *(const uint2*)(b1 + 128);
        uint2 vr2 = *(const uint2*)(b2 + 128);
        uint2 vr3 = *(const uint2*)(b3 + 128);

        float sc0 = edge_score(qv, bf2f(kr0.x), bf2f(kr0.y));
        float sc1 = edge_score(qv, bf2f(kr1.x), bf2f(kr1.y));
        float sc2 = edge_score(qv, bf2f(kr2.x), bf2f(kr2.y));
        float sc3 = edge_score(qv, bf2f(kr3.x), bf2f(kr3.y));

        z0 += sc0 + sc2;
        z1 += sc1 + sc3;

        float2 v00 = bf2f(vr0.x), v01 = bf2f(vr0.y);
        float2 v10 = bf2f(vr1.x), v11 = bf2f(vr1.y);
        float2 v20 = bf2f(vr2.x), v21 = bf2f(vr2.y);
        float2 v30 = bf2f(vr3.x), v31 = bf2f(vr3.y);

        accA.x += sc0 * v00.x + sc2 * v20.x;
        accA.y += sc0 * v00.y + sc2 * v20.y;
        accA.z += sc0 * v01.x + sc2 * v21.x;
        accA.w += sc0 * v01.y + sc2 * v21.y;
        accB.x += sc1 * v10.x + sc3 * v30.x;
        accB.y += sc1 * v10.y + sc3 * v30.y;
        accB.z += sc1 * v11.x + sc3 * v31.x;
        accB.w += sc1 * v11.y + sc3 * v31.y;
    }
    for (; e < e1; e++) {
        int src = __ldg(esrc + e);
        const __nv_bfloat16* b = kv + (size_t)src * 256 + lane * 4;
        uint2 kr = *(const uint2*)b;
        uint2 vr = *(const uint2*)(b + 128);
        float sc = edge_score(qv, bf2f(kr.x), bf2f(kr.y));
        float2 v0 = bf2f(vr.x);
        float2 v1 = bf2f(vr.y);
        z0 += sc;
        accA.x += sc * v0.x;
        accA.y += sc * v0.y;
        accA.z += sc * v1.x;
        accA.w += sc * v1.y;
    }

    float z = z0 + z1;
    float inv = 1.0f / (z + 1e-6f);
    float xs[4] = {(accA.x + accB.x) * inv, (accA.y + accB.y) * inv,
                   (accA.z + accB.z) * inv, (accA.w + accB.w) * inv};
    uint2 phi, plo;
    pack_hilo4(xs, phi, plo);
    size_t obase = (size_t)node * HID + lane * 4;
    *(uint2*)&ohi[obase] = phi;
    *(uint2*)&olo[obase] = plo;
}

// ============================================================================
// Shared GEMM mainloop (BM=128, BN=128, BK=32, double-buffered cp.async)
// All GEMMs 3-term: 2-term drops a COHERENT ~2^-9 perturbation that does NOT
// attenuate downstream (verified R11/R12 failures).
// ============================================================================
#define GEMM_SMEM 81920
#define STG_H 20480  // halves per stage

#define GEMM_LOAD_STAGE(k0, base)                                                   \
    {                                                                               \
        _Pragma("unroll") for (int j = 0; j < 2; j++) {                             \
            int r = r_ld + j * 64;                                                  \
            int gm = m0 + r;                                                        \
            int gmc = (gm < M) ? gm : 0;                                            \
            int sza = (gm < M) ? 16 : 0;                                            \
            unsigned dA = smb + (unsigned)((base) + r * 40 + cc_ld) * 2;            \
            cp16(dA, Ahi + (size_t)gmc * K + (k0) + cc_ld, sza);                    \
            cp16(dA + 10240, Alo + (size_t)gmc * K + (k0) + cc_ld, sza);            \
            int gn = n0 + r;                                                        \
            int gnc = (gn < N) ? gn : 0;                                            \
            int szb = (gn < N) ? 16 : 0;                                            \
            unsigned dB = smb + (unsigned)((base) + 10240 + r * 40 + cc_ld) * 2;    \
            cp16(dB, Bhi + (size_t)gnc * K + (k0) + cc_ld, szb);                    \
            cp16(dB + 10240, Blo + (size_t)gnc * K + (k0) + cc_ld, szb);            \
        }                                                                           \
        asm volatile("cp.async.commit_group;");                                     \
    }

#define GEMM_COMPUTE_STAGE(base)                                                    \
    {                                                                               \
        _Pragma("unroll") for (int kk = 0; kk < 32; kk += 16) {                     \
            unsigned ah[2][4], al[2][4];                                            \
            _Pragma("unroll") for (int mt = 0; mt < 2; mt++) {                      \
                int row = wm0 + mt * 16 + a_row;                                    \
                ldmx4(ah[mt], sm + (base) + row * 40 + kk + a_kc);                  \
                ldmx4(al[mt], sm + (base) + 5120 + row * 40 + kk + a_kc);           \
            }                                                                       \
            _Pragma("unroll") for (int p4 = 0; p4 < 4; p4++) {                      \
                unsigned bh[4], bl[4];                                              \
                int row = wn0 + p4 * 16 + b_row;                                    \
                ldmx4(bh, sm + (base) + 10240 + row * 40 + kk + b_kc);              \
                ldmx4(bl, sm + (base) + 15360 + row * 40 + kk + b_kc);              \
                _Pragma("unroll") for (int sub = 0; sub < 2; sub++) {               \
                    int nt = p4 * 2 + sub;                                          \
                    unsigned b0 = bh[sub * 2], b1 = bh[sub * 2 + 1];                \
                    unsigned c0 = bl[sub * 2], c1 = bl[sub * 2 + 1];                \
                    _Pragma("unroll") for (int mt = 0; mt < 2; mt++) {              \
                        mma16816(acc[mt][nt], ah[mt], b0, b1);                      \
                        mma16816(acc[mt][nt], ah[mt], c0, c1);                      \
                        mma16816(acc[mt][nt], al[mt], b0, b1);                      \
                    }                                                               \
                }                                                                   \
            }                                                                       \
        }                                                                           \
    }

#define GEMM_MAINLOOP()                                                             \
    GEMM_LOAD_STAGE(0, 0);                                                          \
    int buf = 0;                                                                    \
    int nIter = K >> 5;                                                             \
    for (int it = 0; it < nIter; it++) {                                            \
        if (it + 1 < nIter) {                                                       \
            GEMM_LOAD_STAGE((it + 1) * 32, (buf ^ 1) * STG_H);                      \
            asm volatile("cp.async.wait_group 1;");                                 \
        } else {                                                                    \
            asm volatile("cp.async.wait_group 0;");                                 \
        }                                                                           \
        __syncthreads();                                                            \
        GEMM_COMPUTE_STAGE(buf * STG_H);                                            \
        __syncthreads();                                                            \
        buf ^= 1;                                                                   \
    }

#define GEMM_PREAMBLE()                                                             \
    extern __shared__ __nv_bfloat16 sm[];                                           \
    unsigned smb = (unsigned)__cvta_generic_to_shared(sm);                          \
    int t = threadIdx.x, lane = t & 31, w = t >> 5;                                 \
    int m0 = blockIdx.x * 128, n0 = blockIdx.y * 128;                               \
    int wm0 = (w >> 1) * 32;                                                        \
    int wn0 = (w & 1) * 64;                                                         \
    float acc[2][8][4];                                                             \
    _Pragma("unroll") for (int mt = 0; mt < 2; mt++)                                \
        _Pragma("unroll") for (int nt = 0; nt < 8; nt++)                            \
            _Pragma("unroll") for (int i = 0; i < 4; i++) acc[mt][nt][i] = 0.f;     \
    int grp = lane >> 3, lrow = lane & 7;                                           \
    int a_row = lrow + (grp & 1) * 8;                                               \
    int a_kc = (grp >> 1) * 8;                                                      \
    int b_row = lrow + (grp >> 1) * 8;                                              \
    int b_kc = (grp & 1) * 8;                                                       \
    int r_ld = t >> 2;                                                              \
    int cc_ld = (t & 3) * 8;

// ---------------- plain tc GEMM (bias/relu; f32 and/or hi-lo; optional QKV-split out) ----------------
__global__ void __launch_bounds__(256, 2) gemm_tc2_kernel(
    const __nv_bfloat16* __restrict__ Ahi, const __nv_bfloat16* __restrict__ Alo,
    const __nv_bfloat16* __restrict__ Bhi, const __nv_bfloat16* __restrict__ Blo,
    const float* __restrict__ bias, float* __restrict__ C,
    __nv_bfloat16* __restrict__ Chi, __nv_bfloat16* __restrict__ Clo,
    int M, int K, int N, int relu,
    float* __restrict__ Q, __nv_bfloat16* __restrict__ KV) {
    GEMM_PREAMBLE();
    GEMM_MAINLOOP();

    int rr = lane >> 2, c2 = (lane & 3) * 2;
    if (KV) {
#pragma unroll
        for (int mt = 0; mt < 2; mt++) {
#pragma unroll
            for (int nt = 0; nt < 8; nt++) {
                int n = n0 + wn0 + nt * 8 + c2;
#pragma unroll
                for (int half = 0; half < 2; half++) {
                    int m = m0 + wm0 + mt * 16 + rr + half * 8;
                    if (m >= M) continue;
                    float v0 = acc[mt][nt][half * 2];
                    float v1 = acc[mt][nt][half * 2 + 1];
                    if (n < 128) {
                        *(float2*)&Q[(size_t)m * 128 + n] = make_float2(v0, v1);
                    } else {
                        __nv_bfloat162 p;
                        p.x = __float2bfloat16(v0);
                        p.y = __float2bfloat16(v1);
                        *(__nv_bfloat162*)&KV[(size_t)m * 256 + (n - 128)] = p;
                    }
                }
            }
        }
        return;
    }
#pragma unroll
    for (int mt = 0; mt < 2; mt++) {
#pragma unroll
        for (int nt = 0; nt < 8; nt++) {
            int n = n0 + wn0 + nt * 8 + c2;
            if (n >= N) continue;
            float bx = 0.f, by = 0.f;
            if (bias) { bx = bias[n]; by = bias[n + 1]; }
#pragma unroll
            for (int half = 0; half < 2; half++) {
                int m = m0 + wm0 + mt * 16 + rr + half * 8;
                if (m >= M) continue;
                float v0 = acc[mt][nt][half * 2] + bx;
                float v1 = acc[mt][nt][half * 2 + 1] + by;
                if (relu) { v0 = fmaxf(v0, 0.f); v1 = fmaxf(v1, 0.f); }
                if (C) *(float2*)&C[(size_t)m * N + n] = make_float2(v0, v1);
                if (Chi) {
                    __nv_bfloat16 h0, l0, h1, l1;
                    split_bf16(v0, h0, l0);
                    split_bf16(v1, h1, l1);
                    __nv_bfloat162 ph, pl;
                    ph.x = h0; ph.y = h1;
                    pl.x = l0; pl.y = l1;
                    *(__nv_bfloat162*)&Chi[(size_t)m * N + n] = ph;
                    *(__nv_bfloat162*)&Clo[(size_t)m * N + n] = pl;
                }
            }
        }
    }
}

// ---------------- fused GEMM + bias + residual(hi/lo) + LayerNorm (N=128) ----------------
__global__ void __launch_bounds__(256, 2) gemm_ln_kernel(
    const __nv_bfloat16* __restrict__ Ahi, const __nv_bfloat16* __restrict__ Alo,
    const __nv_bfloat16* __restrict__ Bhi, const __nv_bfloat16* __restrict__ Blo,
    const float* __restrict__ bias,
    const __nv_bfloat16* __restrict__ resHi, const __nv_bfloat16* __restrict__ resLo,
    const float* __restrict__ lng, const float* __restrict__ lnb,
    __nv_bfloat16* __restrict__ outHi, __nv_bfloat16* __restrict__ outLo, int M, int K) {
    const int N = 128;
    GEMM_PREAMBLE();
    GEMM_MAINLOOP();

    __shared__ float red[128][4];
    int rr = lane >> 2, c2 = (lane & 3) * 2;

    float sums[2][2] = {{0.f, 0.f}, {0.f, 0.f}};
    float sqs[2][2] = {{0.f, 0.f}, {0.f, 0.f}};
#pragma unroll
    for (int mt = 0; mt < 2; mt++) {
#pragma unroll
        for (int nt = 0; nt < 8; nt++) {
            int n = wn0 + nt * 8 + c2;
            float bx = bias[n], by = bias[n + 1];
#pragma unroll
            for (int half = 0; half < 2; half++) {
                int m = m0 + wm0 + mt * 16 + rr + half * 8;
                int mc = (m < M) ? m : 0;
                float2 rh = __bfloat1622float2(*(const __nv_bfloat162*)&resHi[(size_t)mc * N + n]);
                float2 rl = __bfloat1622float2(*(const __nv_bfloat162*)&resLo[(size_t)mc * N + n]);
                float v0 = acc[mt][nt][half * 2] + bx + rh.x + rl.x;
                float v1 = acc[mt][nt][half * 2 + 1] + by + rh.y + rl.y;
                acc[mt][nt][half * 2] = v0;
                acc[mt][nt][half * 2 + 1] = v1;
                sums[mt][half] += v0 + v1;
                sqs[mt][half] += v0 * v0 + v1 * v1;
            }
        }
    }
#pragma unroll
    for (int mt = 0; mt < 2; mt++)
#pragma unroll
        for (int half = 0; half < 2; half++) {
            float s = sums[mt][half], q = sqs[mt][half];
            s += __shfl_xor_sync(0xffffffffu, s, 1);
            s += __shfl_xor_sync(0xffffffffu, s, 2);
            q += __shfl_xor_sync(0xffffffffu, q, 1);
            q += __shfl_xor_sync(0xffffffffu, q, 2);
            sums[mt][half] = s;
            sqs[mt][half] = q;
        }
    if ((lane & 3) == 0) {
#pragma unroll
        for (int mt = 0; mt < 2; mt++)
#pragma unroll
            for (int half = 0; half < 2; half++) {
                int row = wm0 + mt * 16 + rr + half * 8;
                red[row][(w & 1) * 2] = sums[mt][half];
                red[row][(w & 1) * 2 + 1] = sqs[mt][half];
            }
    }
    __syncthreads();

#pragma unroll
    for (int mt = 0; mt < 2; mt++) {
#pragma unroll
        for (int half = 0; half < 2; half++) {
            int row = wm0 + mt * 16 + rr + half * 8;
            float s = red[row][0] + red[row][2];
            float q = red[row][1] + red[row][3];
            float mu = s * (1.0f / 128.0f);
            float var = q * (1.0f / 128.0f) - mu * mu;
            float rstd = rsqrtf(var + 1e-5f);
            int m = m0 + row;
            if (m >= M) continue;
#pragma unroll
            for (int nt = 0; nt < 8; nt++) {
                int n = wn0 + nt * 8 + c2;
                float gx = lng[n], gy = lng[n + 1];
                float bx = lnb[n], by = lnb[n + 1];
                float v0 = (acc[mt][nt][half * 2] - mu) * rstd * gx + bx;
                float v1 = (acc[mt][nt][half * 2 + 1] - mu) * rstd * gy + by;
                __nv_bfloat16 h0, l0, h1, l1;
                split_bf16(v0, h0, l0);
                split_bf16(v1, h1, l1);
                __nv_bfloat162 ph, pl;
                ph.x = h0; ph.y = h1;
                pl.x = l0; pl.y = l1;
                *(__nv_bfloat162*)&outHi[(size_t)m * N + n] = ph;
                *(__nv_bfloat162*)&outLo[(size_t)m * N + n] = pl;
            }
        }
    }
}

static void gemm_tc(const __nv_bfloat16* Ahi, const __nv_bfloat16* Alo,
                    const __nv_bfloat16* Bhi, const __nv_bfloat16* Blo,
                    const float* bias, float* C, __nv_bfloat16* Chi, __nv_bfloat16* Clo,
                    int M, int K, int N, int relu, float* Q = nullptr,
                    __nv_bfloat16* KV = nullptr) {
    cudaFuncSetAttribute(gemm_tc2_kernel, cudaFuncAttributeMaxDynamicSharedMemorySize, GEMM_SMEM);
    dim3 grid((M + 127) / 128, (N + 127) / 128);
    gemm_tc2_kernel<<<grid, 256, GEMM_SMEM>>>(Ahi, Alo, Bhi, Blo, bias, C, Chi, Clo,
                                              M, K, N, relu, Q, KV);
}

static void gemm_ln(const __nv_bfloat16* Ahi, const __nv_bfloat16* Alo,
                    const __nv_bfloat16* Bhi, const __nv_bfloat16* Blo,
                    const float* bias, const __nv_bfloat16* resHi, const __nv_bfloat16* resLo,
                    const float* lng, const float* lnb,
                    __nv_bfloat16* outHi, __nv_bfloat16* outLo, int M, int K) {
    cudaFuncSetAttribute(gemm_ln_kernel, cudaFuncAttributeMaxDynamicSharedMemorySize, GEMM_SMEM);
    dim3 grid((M + 127) / 128, 1);
    gemm_ln_kernel<<<grid, 256, GEMM_SMEM>>>(Ahi, Alo, Bhi, Blo, bias, resHi, resLo,
                                             lng, lnb, outHi, outLo, M, K);
}

// ---------------- SIMT fallback GEMM (small N readout tail) ----------------
#define BMg 64
#define BNg 64
#define BKg 16
__global__ void __launch_bounds__(256) gemm_kernel(
    const float* __restrict__ A, const float* __restrict__ B,
    const float* __restrict__ bias, float* __restrict__ C, int M, int K, int N, int relu) {
    __shared__ float As[BKg][BMg + 1];
    __shared__ float Bs[BKg][BNg];

    int t = threadIdx.x;
    int m0 = blockIdx.x * BMg;
    int n0 = blockIdx.y * BNg;
    int ty = t >> 4;
    int tx = t & 15;

    int arow = t >> 2;
    int akc = (t & 3) * 4;
    int brow = t >> 4;
    int bnc = (t & 15) * 4;

    unsigned long long acc[4][2];
#pragma unroll
    for (int i = 0; i < 4; i++) { acc[i][0] = 0ull; acc[i][1] = 0ull; }

    for (int k0 = 0; k0 < K; k0 += BKg) {
        float4 av = make_float4(0.f, 0.f, 0.f, 0.f);
        if (m0 + arow < M) av = *(const float4*)&A[(size_t)(m0 + arow) * K + k0 + akc];
        As[akc + 0][arow] = av.x;
        As[akc + 1][arow] = av.y;
        As[akc + 2][arow] = av.z;
        As[akc + 3][arow] = av.w;

        float4 bv = make_float4(0.f, 0.f, 0.f, 0.f);
        if (n0 + bnc < N) bv = *(const float4*)&B[(size_t)(k0 + brow) * N + n0 + bnc];
        *(float4*)&Bs[brow][bnc] = bv;

        __syncthreads();
#pragma unroll
        for (int kk = 0; kk < BKg; kk++) {
            unsigned long long b0 = *(const unsigned long long*)&Bs[kk][tx * 4];
            unsigned long long b1 = *(const unsigned long long*)&Bs[kk][tx * 4 + 2];
            const float* ap = &As[kk][ty * 4];
#pragma unroll
            for (int i = 0; i < 4; i++) {
                unsigned long long aa = pack2(ap[i]);
                fma2(acc[i][0], aa, b0, acc[i][0]);
                fma2(acc[i][1], aa, b1, acc[i][1]);
            }
        }
        __syncthreads();
    }

#pragma unroll
    for (int i = 0; i < 4; i++) {
        int m = m0 + ty * 4 + i;
        if (m >= M) continue;
        float vals[4];
        unpack2(acc[i][0], vals[0], vals[1]);
        unpack2(acc[i][1], vals[2], vals[3]);
#pragma unroll
        for (int j = 0; j < 4; j++) {
            int n = n0 + tx * 4 + j;
            if (n >= N) continue;
            float val = vals[j];
            if (bias) val += bias[n];
            if (relu) val = fmaxf(val, 0.0f);
            C[(size_t)m * N + n] = val;
        }
    }
}

static void gemm_simt(const float* A, const float* B, const float* bias,
                      float* C, int M, int K, int N, int relu) {
    dim3 grid((M + BMg - 1) / BMg, (N + BNg - 1) / BNg);
    gemm_kernel<<<grid, 256>>>(A, B, bias, C, M, K, N, relu);
}

// ---------------- driver ----------------
extern "C" void kernel_launch(void* const* d_in, const int* in_sizes, int n_in,
                              void* d_out, int out_size) {
    const int* feat = (const int*)d_in[0];
    const int* esrc = (const int*)d_in[1];
    const int* edst = (const int*)d_in[2];
    const float* emb = (const float*)d_in[3];
    const float* Wq = (const float*)d_in[4];
    const float* Wk = (const float*)d_in[5];
    const float* Wv = (const float*)d_in[6];
    const float* Wo = (const float*)d_in[7];
    const float* bo = (const float*)d_in[8];
    const float* ln1_g = (const float*)d_in[9];
    const float* ln1_b = (const float*)d_in[10];
    const float* W1 = (const float*)d_in[11];
    const float* b1 = (const float*)d_in[12];
    const float* W2 = (const float*)d_in[13];
    const float* b2 = (const float*)d_in[14];
    const float* ln2_g = (const float*)d_in[15];
    const float* ln2_b = (const float*)d_in[16];
    const float* mW0 = (const float*)d_in[17];
    const float* mb0 = (const float*)d_in[18];
    const float* mW1 = (const float*)d_in[19];
    const float* mb1 = (const float*)d_in[20];
    const float* mW2 = (const float*)d_in[21];
    const float* mb2 = (const float*)d_in[22];
    float* out = (float*)d_out;

    float *q, *t0, *t1;
    int* rp;
    __nv_bfloat16 *kv;
    __nv_bfloat16 *h_hi, *h_lo, *attn_hi, *attn_lo, *mid_hi, *mid_lo;
    __nv_bfloat16 *wqkv_hi, *wqkv_lo, *wo_hi, *wo_lo, *w1_hi, *w1_lo, *w2_hi, *w2_lo, *m0_hi, *m0_lo;
    cudaGetSymbolAddress((void**)&q, g_q);
    cudaGetSymbolAddress((void**)&kv, g_kv);
    cudaGetSymbolAddress((void**)&t0, g_t0);
    cudaGetSymbolAddress((void**)&t1, g_t1);
    cudaGetSymbolAddress((void**)&rp, g_rowptr);
    cudaGetSymbolAddress((void**)&h_hi, g_h_hi);
    cudaGetSymbolAddress((void**)&h_lo, g_h_lo);
    cudaGetSymbolAddress((void**)&attn_hi, g_attn_hi);
    cudaGetSymbolAddress((void**)&attn_lo, g_attn_lo);
    cudaGetSymbolAddress((void**)&mid_hi, g_mid_hi);
    cudaGetSymbolAddress((void**)&mid_lo, g_mid_lo);
    cudaGetSymbolAddress((void**)&wqkv_hi, g_wqkv_hi);
    cudaGetSymbolAddress((void**)&wqkv_lo, g_wqkv_lo);
    cudaGetSymbolAddress((void**)&wo_hi, g_wo_hi);
    cudaGetSymbolAddress((void**)&wo_lo, g_wo_lo);
    cudaGetSymbolAddress((void**)&w1_hi, g_w1_hi);
    cudaGetSymbolAddress((void**)&w1_lo, g_w1_lo);
    cudaGetSymbolAddress((void**)&w2_hi, g_w2_hi);
    cudaGetSymbolAddress((void**)&w2_lo, g_w2_lo);
    cudaGetSymbolAddress((void**)&m0_hi, g_m0_hi);
    cudaGetSymbolAddress((void**)&m0_lo, g_m0_lo);

    // launch 1: square weights + readout m0
    {
        int tot = 4 * SQ_TOT + HID * 64;
        splitw_a_kernel<<<(tot + 255) / 256, 256>>>(Wq, Wk, Wv, Wo, mW0, wqkv_hi, wqkv_lo,
                                                    wo_hi, wo_lo, m0_hi, m0_lo);
    }
    // launch 2: FFN weights
    {
        int tot = 2 * RT_TOT;
        splitw_b_kernel<<<(tot + 255) / 256, 256>>>(W1, W2, w1_hi, w1_lo, w2_hi, w2_lo);
    }

    int warp_threads = N_NODES * 32;
    int wblocks = (warp_threads + 255) / 256;

    // launch 3
    rowptr_kernel<<<(N_NODES + 1 + 255) / 256, 256>>>(edst, rp);
    // launch 4
    embed_kernel<<<wblocks, 256>>>(feat, emb, h_hi, h_lo);

    for (int l = 0; l < N_LAYERS; l++) {
        const __nv_bfloat16* wqkvh = wqkv_hi + (size_t)l * 3 * HID * HID;
        const __nv_bfloat16* wqkvl = wqkv_lo + (size_t)l * 3 * HID * HID;
        const __nv_bfloat16* woh = wo_hi + (size_t)l * HID * HID;
        const __nv_bfloat16* wol = wo_lo + (size_t)l * HID * HID;
        const __nv_bfloat16* w1h = w1_hi + (size_t)l * 2 * HID * HID;
        const __nv_bfloat16* w1l = w1_lo + (size_t)l * 2 * HID * HID;
        const __nv_bfloat16* w2h = w2_hi + (size_t)l * HID * 2 * HID;
        const __nv_bfloat16* w2l = w2_lo + (size_t)l * HID * 2 * HID;

        // fused QKV -> q fp32 + kv bf16
        gemm_tc(h_hi, h_lo, wqkvh, wqkvl, nullptr, nullptr, nullptr, nullptr,
                N_NODES, HID, 3 * HID, 0, q, kv);

        attn_kernel<<<wblocks, 256>>>(q, kv, rp, esrc, attn_hi, attn_lo);

        // h = LN1(h + attn @ Wo + bo)
        gemm_ln(attn_hi, attn_lo, woh, wol, bo + l * HID, h_hi, h_lo,
                ln1_g + l * HID, ln1_b + l * HID, h_hi, h_lo, N_NODES, HID);
        // mid = relu(h @ W1 + b1)
        gemm_tc(h_hi, h_lo, w1h, w1l, b1 + l * 2 * HID, nullptr, mid_hi, mid_lo,
                N_NODES, HID, 2 * HID, 1);
        // h = LN2(h + mid @ W2 + b2)
        gemm_ln(mid_hi, mid_lo, w2h, w2l, b2 + l * HID, h_hi, h_lo,
                ln2_g + l * HID, ln2_b + l * HID, h_hi, h_lo, N_NODES, 2 * HID);
    }

    // readout: 128 -> 64 (tc) -> 32 -> 16 (SIMT)
    gemm_tc(h_hi, h_lo, m0_hi, m0_lo, mb0, t0, nullptr, nullptr, N_NODES, HID, 64, 1);
    gemm_simt(t0, mW1, mb1, t1, N_NODES, 64, 32, 1);
    gemm_simt(t1, mW2, mb2, out, N_NODES, 32, N_CLASSES, 0);
}

// round 16
// speedup vs baseline: 1.1233x; 1.0508x over previous
#include <cuda_runtime.h>
#include <cuda_bf16.h>
#include <math.h>

#define N_NODES 100000
#define N_EDGES 1600000
#define HID 128
#define HEADS 8
#define N_LAYERS 4
#define IN_DIM 32
#define N_CLASSES 16

// ---------------- scratch (device globals; no allocation allowed) ----------------
__device__ float g_q[N_NODES * HID];
__device__ __nv_bfloat16 g_kv[N_NODES * 2 * HID];   // k then v, bf16, per node
__device__ float g_t0[N_NODES * 64];
__device__ float g_t1[N_NODES * 32];
__device__ int g_rowptr[N_NODES + 1];

// bf16 hi/lo activation buffers (hi+lo reconstructs ~fp32)
__device__ __nv_bfloat16 g_h_hi[N_NODES * HID];
__device__ __nv_bfloat16 g_h_lo[N_NODES * HID];
__device__ __nv_bfloat16 g_attn_hi[N_NODES * HID];
__device__ __nv_bfloat16 g_attn_lo[N_NODES * HID];
__device__ __nv_bfloat16 g_mid_hi[N_NODES * 2 * HID];
__device__ __nv_bfloat16 g_mid_lo[N_NODES * 2 * HID];

// bf16 hi/lo transposed weights (B^T layout: [rows=N][cols=K])
__device__ __nv_bfloat16 g_wqkv_hi[N_LAYERS * 3 * HID * HID];
__device__ __nv_bfloat16 g_wqkv_lo[N_LAYERS * 3 * HID * HID];
__device__ __nv_bfloat16 g_wo_hi[N_LAYERS * HID * HID];
__device__ __nv_bfloat16 g_wo_lo[N_LAYERS * HID * HID];
__device__ __nv_bfloat16 g_w1_hi[N_LAYERS * 2 * HID * HID];
__device__ __nv_bfloat16 g_w1_lo[N_LAYERS * 2 * HID * HID];
__device__ __nv_bfloat16 g_w2_hi[N_LAYERS * HID * 2 * HID];
__device__ __nv_bfloat16 g_w2_lo[N_LAYERS * HID * 2 * HID];
__device__ __nv_bfloat16 g_m0_hi[64 * HID];
__device__ __nv_bfloat16 g_m0_lo[64 * HID];

// ---------------- helpers ----------------
__device__ __forceinline__ void split_bf16(float x, __nv_bfloat16& hi, __nv_bfloat16& lo) {
    hi = __float2bfloat16(x);
    lo = __float2bfloat16(x - __bfloat162float(hi));
}
__device__ __forceinline__ void ldmx4(unsigned r[4], const void* p) {
    unsigned addr = (unsigned)__cvta_generic_to_shared(p);
    asm volatile("ldmatrix.sync.aligned.m8n8.x4.shared.b16 {%0,%1,%2,%3}, [%4];"
                 : "=r"(r[0]), "=r"(r[1]), "=r"(r[2]), "=r"(r[3])
                 : "r"(addr));
}
__device__ __forceinline__ void mma16816(float d[4], const unsigned a[4],
                                         unsigned b0, unsigned b1) {
    asm volatile(
        "mma.sync.aligned.m16n8k16.row.col.f32.bf16.bf16.f32 "
        "{%0,%1,%2,%3},{%4,%5,%6,%7},{%8,%9},{%0,%1,%2,%3};"
        : "+f"(d[0]), "+f"(d[1]), "+f"(d[2]), "+f"(d[3])
        : "r"(a[0]), "r"(a[1]), "r"(a[2]), "r"(a[3]), "r"(b0), "r"(b1));
}
__device__ __forceinline__ void cp16(unsigned dst, const void* src, int sz) {
    asm volatile("cp.async.cg.shared.global [%0], [%1], 16, %2;"
                 :: "r"(dst), "l"(src), "r"(sz));
}
__device__ __forceinline__ void fma2(unsigned long long& d, unsigned long long a,
                                     unsigned long long b, unsigned long long c) {
    asm("fma.rn.f32x2 %0, %1, %2, %3;" : "=l"(d) : "l"(a), "l"(b), "l"(c));
}
__device__ __forceinline__ unsigned long long pack2(float x) {
    unsigned long long d;
    unsigned u = __float_as_uint(x);
    asm("mov.b64 %0, {%1, %2};" : "=l"(d) : "r"(u), "r"(u));
    return d;
}
__device__ __forceinline__ void unpack2(unsigned long long v, float& lo, float& hi) {
    unsigned a, b;
    asm("mov.b64 {%0, %1}, %2;" : "=r"(a), "=r"(b) : "l"(v));
    lo = __uint_as_float(a);
    hi = __uint_as_float(b);
}
// pack 4 floats into hi-uint2 and lo-uint2 (bf16x2 pairs)
__device__ __forceinline__ void pack_hilo4(const float* xs, uint2& phi, uint2& plo) {
    __nv_bfloat16 h[4], l[4];
#pragma unroll
    for (int i = 0; i < 4; i++) split_bf16(xs[i], h[i], l[i]);
    __nv_bfloat162 h01, h23, l01, l23;
    h01.x = h[0]; h01.y = h[1];
    h23.x = h[2]; h23.y = h[3];
    l01.x = l[0]; l01.y = l[1];
    l23.x = l[2]; l23.y = l[3];
    phi.x = *(unsigned*)&h01;
    phi.y = *(unsigned*)&h23;
    plo.x = *(unsigned*)&l01;
    plo.y = *(unsigned*)&l23;
}
__device__ __forceinline__ float2 bf2f(unsigned u) {
    return __bfloat1622float2(*(__nv_bfloat162*)&u);
}

// ---------------- weight split+transpose (consolidated into 2 launches) ----------------
__device__ __forceinline__ void splitw_store(const float* W, __nv_bfloat16* hi,
                                             __nv_bfloat16* lo, int idx, int K, int N,
                                             int lsRows, int rowOff) {
    int l = idx / (K * N);
    int rem = idx - l * K * N;
    int k = rem / N;
    int n = rem - k * N;
    float x = W[idx];
    __nv_bfloat16 h, lw;
    split_bf16(x, h, lw);
    size_t d = ((size_t)(l * lsRows + rowOff + n)) * K + k;
    hi[d] = h;
    lo[d] = lw;
}

// kernel A: Wq, Wk, Wv, Wo, mW0
#define SQ_TOT (N_LAYERS * HID * HID)
__global__ void splitw_a_kernel(const float* __restrict__ Wq, const float* __restrict__ Wk,
                                const float* __restrict__ Wv, const float* __restrict__ Wo,
                                const float* __restrict__ mW0,
                                __nv_bfloat16* __restrict__ qkv_hi, __nv_bfloat16* __restrict__ qkv_lo,
                                __nv_bfloat16* __restrict__ wo_hi, __nv_bfloat16* __restrict__ wo_lo,
                                __nv_bfloat16* __restrict__ m0_hi, __nv_bfloat16* __restrict__ m0_lo) {
    int idx = blockIdx.x * blockDim.x + threadIdx.x;
    if (idx < SQ_TOT) {
        splitw_store(Wq, qkv_hi, qkv_lo, idx, HID, HID, 3 * HID, 0);
        return;
    }
    idx -= SQ_TOT;
    if (idx < SQ_TOT) {
        splitw_store(Wk, qkv_hi, qkv_lo, idx, HID, HID, 3 * HID, HID);
        return;
    }
    idx -= SQ_TOT;
    if (idx < SQ_TOT) {
        splitw_store(Wv, qkv_hi, qkv_lo, idx, HID, HID, 3 * HID, 2 * HID);
        return;
    }
    idx -= SQ_TOT;
    if (idx < SQ_TOT) {
        splitw_store(Wo, wo_hi, wo_lo, idx, HID, HID, HID, 0);
        return;
    }
    idx -= SQ_TOT;
    if (idx < HID * 64) {
        splitw_store(mW0, m0_hi, m0_lo, idx, HID, 64, 64, 0);
    }
}

// kernel B: W1, W2
#define RT_TOT (N_LAYERS * HID * 2 * HID)
__global__ void splitw_b_kernel(const float* __restrict__ W1, const float* __restrict__ W2,
                                __nv_bfloat16* __restrict__ w1_hi, __nv_bfloat16* __restrict__ w1_lo,
                                __nv_bfloat16* __restrict__ w2_hi, __nv_bfloat16* __restrict__ w2_lo) {
    int idx = blockIdx.x * blockDim.x + threadIdx.x;
    if (idx < RT_TOT) {
        splitw_store(W1, w1_hi, w1_lo, idx, HID, 2 * HID, 2 * HID, 0);
        return;
    }
    idx -= RT_TOT;
    if (idx < RT_TOT) {
        splitw_store(W2, w2_hi, w2_lo, idx, 2 * HID, HID, HID, 0);
    }
}

// ---------------- embedding gather (hi/lo, vectorized stores) ----------------
__global__ void embed_kernel(const int* __restrict__ feat, const float* __restrict__ emb,
                             __nv_bfloat16* __restrict__ hhi, __nv_bfloat16* __restrict__ hlo) {
    int idx = blockIdx.x * blockDim.x + threadIdx.x;
    if (idx >= N_NODES * 32) return;
    int n = idx >> 5, c4 = idx & 31;
    int f = feat[n];
    float4 v = ((const float4*)emb)[f * 32 + c4];
    float xs[4] = {v.x, v.y, v.z, v.w};
    uint2 phi, plo;
    pack_hilo4(xs, phi, plo);
    size_t base = (size_t)n * HID + c4 * 4;
    *(uint2*)&hhi[base] = phi;
    *(uint2*)&hlo[base] = plo;
}

// ---------------- CSR row pointers from sorted edge_dst ----------------
__global__ void rowptr_kernel(const int* __restrict__ dst, int* __restrict__ rp) {
    int n = blockIdx.x * blockDim.x + threadIdx.x;
    if (n > N_NODES) return;
    if (n == N_NODES) { rp[n] = N_EDGES; return; }
    int lo = 0, hi = N_EDGES;
    while (lo < hi) {
        int mid = (lo + hi) >> 1;
        if (dst[mid] < n) lo = mid + 1; else hi = mid;
    }
    rp[n] = lo;
}

// ---------------- per-node attention: 4-edge unrolled straight-line (R13 form) ----------------
__device__ __forceinline__ float edge_score(float4 qv, float2 k0, float2 k1) {
    float s = k0.x * qv.x + k0.y * qv.y + k1.x * qv.z + k1.y * qv.w;
    s += __shfl_xor_sync(0xffffffffu, s, 1);
    s += __shfl_xor_sync(0xffffffffu, s, 2);
    s *= 0.25f;
    s = fminf(fmaxf(s, -5.0f), 5.0f);
    return __expf(s);
}

__global__ void attn_kernel(const float* __restrict__ q, const __nv_bfloat16* __restrict__ kv,
                            const int* __restrict__ rp, const int* __restrict__ esrc,
                            __nv_bfloat16* __restrict__ ohi, __nv_bfloat16* __restrict__ olo) {
    int gtid = blockIdx.x * blockDim.x + threadIdx.x;
    int node = gtid >> 5;
    int lane = threadIdx.x & 31;
    if (node >= N_NODES) return;

    float4 qv = ((const float4*)q)[node * 32 + lane];
    float z0 = 0.0f, z1 = 0.0f;
    float4 accA = make_float4(0.f, 0.f, 0.f, 0.f);
    float4 accB = make_float4(0.f, 0.f, 0.f, 0.f);

    int e0 = rp[node];
    int e1 = rp[node + 1];
    int e = e0;

    for (; e + 4 <= e1; e += 4) {
        int s0 = __ldg(esrc + e);
        int s1 = __ldg(esrc + e + 1);
        int s2 = __ldg(esrc + e + 2);
        int s3 = __ldg(esrc + e + 3);
        const __nv_bfloat16* b0 = kv + (size_t)s0 * 256 + lane * 4;
        const __nv_bfloat16* b1 = kv + (size_t)s1 * 256 + lane * 4;
        const __nv_bfloat16* b2 = kv + (size_t)s2 * 256 + lane * 4;
        const __nv_bfloat16* b3 = kv + (size_t)s3 * 256 + lane * 4;
        // ptxas front-batches these 8 gathers (MLP=8)
        uint2 kr0 = *(const uint2*)b0;
        uint2 kr1 = *(const uint2*)b1;
        uint2 kr2 = *(const uint2*)b2;
        uint2 kr3 = *(const uint2*)b3;
        uint2 vr0 = *(const uint2*)(b0 + 128);
        uint2 vr1 = *(const uint2*)(b1 + 128);
        uint2 vr2 = *(const uint2*)(b2 + 128);
        uint2 vr3 = *(const uint2*)(b3 + 128);

        float sc0 = edge_score(qv, bf2f(kr0.x), bf2f(kr0.y));
        float sc1 = edge_score(qv, bf2f(kr1.x), bf2f(kr1.y));
        float sc2 = edge_score(qv, bf2f(kr2.x), bf2f(kr2.y));
        float sc3 = edge_score(qv, bf2f(kr3.x), bf2f(kr3.y));

        z0 += sc0 + sc2;
        z1 += sc1 + sc3;

        float2 v00 = bf2f(vr0.x), v01 = bf2f(vr0.y);
        float2 v10 = bf2f(vr1.x), v11 = bf2f(vr1.y);
        float2 v20 = bf2f(vr2.x), v21 = bf2f(vr2.y);
        float2 v30 = bf2f(vr3.x), v31 = bf2f(vr3.y);

        accA.x += sc0 * v00.x + sc2 * v20.x;
        accA.y += sc0 * v00.y + sc2 * v20.y;
        accA.z += sc0 * v01.x + sc2 * v21.x;
        accA.w += sc0 * v01.y + sc2 * v21.y;
        accB.x += sc1 * v10.x + sc3 * v30.x;
        accB.y += sc1 * v10.y + sc3 * v30.y;
        accB.z += sc1 * v11.x + sc3 * v31.x;
        accB.w += sc1 * v11.y + sc3 * v31.y;
    }
    for (; e < e1; e++) {
        int src = __ldg(esrc + e);
        const __nv_bfloat16* b = kv + (size_t)src * 256 + lane * 4;
        uint2 kr = *(const uint2*)b;
        uint2 vr = *(const uint2*)(b + 128);
        float sc = edge_score(qv, bf2f(kr.x), bf2f(kr.y));
        float2 v0 = bf2f(vr.x);
        float2 v1 = bf2f(vr.y);
        z0 += sc;
        accA.x += sc * v0.x;
        accA.y += sc * v0.y;
        accA.z += sc * v1.x;
        accA.w += sc * v1.y;
    }

    float z = z0 + z1;
    float inv = 1.0f / (z + 1e-6f);
    float xs[4] = {(accA.x + accB.x) * inv, (accA.y + accB.y) * inv,
                   (accA.z + accB.z) * inv, (accA.w + accB.w) * inv};
    uint2 phi, plo;
    pack_hilo4(xs, phi, plo);
    size_t obase = (size_t)node * HID + lane * 4;
    *(uint2*)&ohi[obase] = phi;
    *(uint2*)&olo[obase] = plo;
}

// ============================================================================
// Shared GEMM mainloop (BM=128, BN=128, BK=32, double-buffered cp.async)
// NTERMS=3: full hi/lo. NTERMS=2 is ONLY safe for the QKV GEMM: its k/v
// outputs are bf16-rounded anyway and q's coherent 2^-9 error measured +1.9e-5
// marginal (R11 vs R12). W1/m0 2-term measured 1.9e-3 -> keep 3-term there.
// ============================================================================
#define GEMM_SMEM 81920
#define STG_H 20480  // halves per stage

#define GEMM_LOAD_STAGE(k0, base)                                                   \
    {                                                                               \
        _Pragma("unroll") for (int j = 0; j < 2; j++) {                             \
            int r = r_ld + j * 64;                                                  \
            int gm = m0 + r;                                                        \
            int gmc = (gm < M) ? gm : 0;                                            \
            int sza = (gm < M) ? 16 : 0;                                            \
            unsigned dA = smb + (unsigned)((base) + r * 40 + cc_ld) * 2;            \
            cp16(dA, Ahi + (size_t)gmc * K + (k0) + cc_ld, sza);                    \
            if (NTERMS == 3) cp16(dA + 10240, Alo + (size_t)gmc * K + (k0) + cc_ld, sza); \
            int gn = n0 + r;                                                        \
            int gnc = (gn < N) ? gn : 0;                                            \
            int szb = (gn < N) ? 16 : 0;                                            \
            unsigned dB = smb + (unsigned)((base) + 10240 + r * 40 + cc_ld) * 2;    \
            cp16(dB, Bhi + (size_t)gnc * K + (k0) + cc_ld, szb);                    \
            cp16(dB + 10240, Blo + (size_t)gnc * K + (k0) + cc_ld, szb);            \
        }                                                                           \
        asm volatile("cp.async.commit_group;");                                     \
    }

#define GEMM_COMPUTE_STAGE(base)                                                    \
    {                                                                               \
        _Pragma("unroll") for (int kk = 0; kk < 32; kk += 16) {                     \
            unsigned ah[2][4], al[2][4];                                            \
            _Pragma("unroll") for (int mt = 0; mt < 2; mt++) {                      \
                int row = wm0 + mt * 16 + a_row;                                    \
                ldmx4(ah[mt], sm + (base) + row * 40 + kk + a_kc);                  \
                if (NTERMS == 3) ldmx4(al[mt], sm + (base) + 5120 + row * 40 + kk + a_kc); \
            }                                                                       \
            _Pragma("unroll") for (int p4 = 0; p4 < 4; p4++) {                      \
                unsigned bh[4], bl[4];                                              \
                int row = wn0 + p4 * 16 + b_row;                                    \
                ldmx4(bh, sm + (base) + 10240 + row * 40 + kk + b_kc);              \
                ldmx4(bl, sm + (base) + 15360 + row * 40 + kk + b_kc);              \
                _Pragma("unroll") for (int sub = 0; sub < 2; sub++) {               \
                    int nt = p4 * 2 + sub;                                          \
                    unsigned b0 = bh[sub * 2], b1 = bh[sub * 2 + 1];                \
                    unsigned c0 = bl[sub * 2], c1 = bl[sub * 2 + 1];                \
                    _Pragma("unroll") for (int mt = 0; mt < 2; mt++) {              \
                        mma16816(acc[mt][nt], ah[mt], b0, b1);                      \
                        mma16816(acc[mt][nt], ah[mt], c0, c1);                      \
                        if (NTERMS == 3) mma16816(acc[mt][nt], al[mt], b0, b1);     \
                    }                                                               \
                }                                                                   \
            }                                                                       \
        }                                                                           \
    }

#define GEMM_MAINLOOP()                                                             \
    GEMM_LOAD_STAGE(0, 0);                                                          \
    int buf = 0;                                                                    \
    int nIter = K >> 5;                                                             \
    for (int it = 0; it < nIter; it++) {                                            \
        if (it + 1 < nIter) {                                                       \
            GEMM_LOAD_STAGE((it + 1) * 32, (buf ^ 1) * STG_H);                      \
            asm volatile("cp.async.wait_group 1;");                                 \
        } else {                                                                    \
            asm volatile("cp.async.wait_group 0;");                                 \
        }                                                                           \
        __syncthreads();                                                            \
        GEMM_COMPUTE_STAGE(buf * STG_H);                                            \
        __syncthreads();                                                            \
        buf ^= 1;                                                                   \
    }

#define GEMM_PREAMBLE()                                                             \
    extern __shared__ __nv_bfloat16 sm[];                                           \
    unsigned smb = (unsigned)__cvta_generic_to_shared(sm);                          \
    int t = threadIdx.x, lane = t & 31, w = t >> 5;                                 \
    int m0 = blockIdx.x * 128, n0 = blockIdx.y * 128;                               \
    int wm0 = (w >> 1) * 32;                                                        \
    int wn0 = (w & 1) * 64;                                                         \
    float acc[2][8][4];                                                             \
    _Pragma("unroll") for (int mt = 0; mt < 2; mt++)                                \
        _Pragma("unroll") for (int nt = 0; nt < 8; nt++)                            \
            _Pragma("unroll") for (int i = 0; i < 4; i++) acc[mt][nt][i] = 0.f;     \
    int grp = lane >> 3, lrow = lane & 7;                                           \
    int a_row = lrow + (grp & 1) * 8;                                               \
    int a_kc = (grp >> 1) * 8;                                                      \
    int b_row = lrow + (grp >> 1) * 8;                                              \
    int b_kc = (grp & 1) * 8;                                                       \
    int r_ld = t >> 2;                                                              \
    int cc_ld = (t & 3) * 8;

// ---------------- tc GEMM (templated term count; bias/relu; f32 and/or hi-lo; QKV-split out) ----------------
template <int NTERMS>
__global__ void __launch_bounds__(256, 2) gemm_tc2_kernel(
    const __nv_bfloat16* __restrict__ Ahi, const __nv_bfloat16* __restrict__ Alo,
    const __nv_bfloat16* __restrict__ Bhi, const __nv_bfloat16* __restrict__ Blo,
    const float* __restrict__ bias, float* __restrict__ C,
    __nv_bfloat16* __restrict__ Chi, __nv_bfloat16* __restrict__ Clo,
    int M, int K, int N, int relu,
    float* __restrict__ Q, __nv_bfloat16* __restrict__ KV) {
    GEMM_PREAMBLE();
    GEMM_MAINLOOP();

    int rr = lane >> 2, c2 = (lane & 3) * 2;
    if (KV) {
#pragma unroll
        for (int mt = 0; mt < 2; mt++) {
#pragma unroll
            for (int nt = 0; nt < 8; nt++) {
                int n = n0 + wn0 + nt * 8 + c2;
#pragma unroll
                for (int half = 0; half < 2; half++) {
                    int m = m0 + wm0 + mt * 16 + rr + half * 8;
                    if (m >= M) continue;
                    float v0 = acc[mt][nt][half * 2];
                    float v1 = acc[mt][nt][half * 2 + 1];
                    if (n < 128) {
                        *(float2*)&Q[(size_t)m * 128 + n] = make_float2(v0, v1);
                    } else {
                        __nv_bfloat162 p;
                        p.x = __float2bfloat16(v0);
                        p.y = __float2bfloat16(v1);
                        *(__nv_bfloat162*)&KV[(size_t)m * 256 + (n - 128)] = p;
                    }
                }
            }
        }
        return;
    }
#pragma unroll
    for (int mt = 0; mt < 2; mt++) {
#pragma unroll
        for (int nt = 0; nt < 8; nt++) {
            int n = n0 + wn0 + nt * 8 + c2;
            if (n >= N) continue;
            float bx = 0.f, by = 0.f;
            if (bias) { bx = bias[n]; by = bias[n + 1]; }
#pragma unroll
            for (int half = 0; half < 2; half++) {
                int m = m0 + wm0 + mt * 16 + rr + half * 8;
                if (m >= M) continue;
                float v0 = acc[mt][nt][half * 2] + bx;
                float v1 = acc[mt][nt][half * 2 + 1] + by;
                if (relu) { v0 = fmaxf(v0, 0.f); v1 = fmaxf(v1, 0.f); }
                if (C) *(float2*)&C[(size_t)m * N + n] = make_float2(v0, v1);
                if (Chi) {
                    __nv_bfloat16 h0, l0, h1, l1;
                    split_bf16(v0, h0, l0);
                    split_bf16(v1, h1, l1);
                    __nv_bfloat162 ph, pl;
                    ph.x = h0; ph.y = h1;
                    pl.x = l0; pl.y = l1;
                    *(__nv_bfloat162*)&Chi[(size_t)m * N + n] = ph;
                    *(__nv_bfloat162*)&Clo[(size_t)m * N + n] = pl;
                }
            }
        }
    }
}

// ---------------- fused GEMM + bias + residual(hi/lo) + LayerNorm (N=128, 3-term) ----------------
__global__ void __launch_bounds__(256, 2) gemm_ln_kernel(
    const __nv_bfloat16* __restrict__ Ahi, const __nv_bfloat16* __restrict__ Alo,
    const __nv_bfloat16* __restrict__ Bhi, const __nv_bfloat16* __restrict__ Blo,
    const float* __restrict__ bias,
    const __nv_bfloat16* __restrict__ resHi, const __nv_bfloat16* __restrict__ resLo,
    const float* __restrict__ lng, const float* __restrict__ lnb,
    __nv_bfloat16* __restrict__ outHi, __nv_bfloat16* __restrict__ outLo, int M, int K) {
    const int N = 128;
    constexpr int NTERMS = 3;
    GEMM_PREAMBLE();
    GEMM_MAINLOOP();

    __shared__ float red[128][4];
    int rr = lane >> 2, c2 = (lane & 3) * 2;

    float sums[2][2] = {{0.f, 0.f}, {0.f, 0.f}};
    float sqs[2][2] = {{0.f, 0.f}, {0.f, 0.f}};
#pragma unroll
    for (int mt = 0; mt < 2; mt++) {
#pragma unroll
        for (int nt = 0; nt < 8; nt++) {
            int n = wn0 + nt * 8 + c2;
            float bx = bias[n], by = bias[n + 1];
#pragma unroll
            for (int half = 0; half < 2; half++) {
                int m = m0 + wm0 + mt * 16 + rr + half * 8;
                int mc = (m < M) ? m : 0;
                float2 rh = __bfloat1622float2(*(const __nv_bfloat162*)&resHi[(size_t)mc * N + n]);
                float2 rl = __bfloat1622float2(*(const __nv_bfloat162*)&resLo[(size_t)mc * N + n]);
                float v0 = acc[mt][nt][half * 2] + bx + rh.x + rl.x;
                float v1 = acc[mt][nt][half * 2 + 1] + by + rh.y + rl.y;
                acc[mt][nt][half * 2] = v0;
                acc[mt][nt][half * 2 + 1] = v1;
                sums[mt][half] += v0 + v1;
                sqs[mt][half] += v0 * v0 + v1 * v1;
            }
        }
    }
#pragma unroll
    for (int mt = 0; mt < 2; mt++)
#pragma unroll
        for (int half = 0; half < 2; half++) {
            float s = sums[mt][half], q = sqs[mt][half];
            s += __shfl_xor_sync(0xffffffffu, s, 1);
            s += __shfl_xor_sync(0xffffffffu, s, 2);
            q += __shfl_xor_sync(0xffffffffu, q, 1);
            q += __shfl_xor_sync(0xffffffffu, q, 2);
            sums[mt][half] = s;
            sqs[mt][half] = q;
        }
    if ((lane & 3) == 0) {
#pragma unroll
        for (int mt = 0; mt < 2; mt++)
#pragma unroll
            for (int half = 0; half < 2; half++) {
                int row = wm0 + mt * 16 + rr + half * 8;
                red[row][(w & 1) * 2] = sums[mt][half];
                red[row][(w & 1) * 2 + 1] = sqs[mt][half];
            }
    }
    __syncthreads();

#pragma unroll
    for (int mt = 0; mt < 2; mt++) {
#pragma unroll
        for (int half = 0; half < 2; half++) {
            int row = wm0 + mt * 16 + rr + half * 8;
            float s = red[row][0] + red[row][2];
            float q = red[row][1] + red[row][3];
            float mu = s * (1.0f / 128.0f);
            float var = q * (1.0f / 128.0f) - mu * mu;
            float rstd = rsqrtf(var + 1e-5f);
            int m = m0 + row;
            if (m >= M) continue;
#pragma unroll
            for (int nt = 0; nt < 8; nt++) {
                int n = wn0 + nt * 8 + c2;
                float gx = lng[n], gy = lng[n + 1];
                float bx = lnb[n], by = lnb[n + 1];
                float v0 = (acc[mt][nt][half * 2] - mu) * rstd * gx + bx;
                float v1 = (acc[mt][nt][half * 2 + 1] - mu) * rstd * gy + by;
                __nv_bfloat16 h0, l0, h1, l1;
                split_bf16(v0, h0, l0);
                split_bf16(v1, h1, l1);
                __nv_bfloat162 ph, pl;
                ph.x = h0; ph.y = h1;
                pl.x = l0; pl.y = l1;
                *(__nv_bfloat162*)&outHi[(size_t)m * N + n] = ph;
                *(__nv_bfloat162*)&outLo[(size_t)m * N + n] = pl;
            }
        }
    }
}

static void gemm_tc(int terms, const __nv_bfloat16* Ahi, const __nv_bfloat16* Alo,
                    const __nv_bfloat16* Bhi, const __nv_bfloat16* Blo,
                    const float* bias, float* C, __nv_bfloat16* Chi, __nv_bfloat16* Clo,
                    int M, int K, int N, int relu, float* Q = nullptr,
                    __nv_bfloat16* KV = nullptr) {
    dim3 grid((M + 127) / 128, (N + 127) / 128);
    if (terms == 3) {
        cudaFuncSetAttribute(gemm_tc2_kernel<3>, cudaFuncAttributeMaxDynamicSharedMemorySize, GEMM_SMEM);
        gemm_tc2_kernel<3><<<grid, 256, GEMM_SMEM>>>(Ahi, Alo, Bhi, Blo, bias, C, Chi, Clo,
                                                     M, K, N, relu, Q, KV);
    } else {
        cudaFuncSetAttribute(gemm_tc2_kernel<2>, cudaFuncAttributeMaxDynamicSharedMemorySize, GEMM_SMEM);
        gemm_tc2_kernel<2><<<grid, 256, GEMM_SMEM>>>(Ahi, Alo, Bhi, Blo, bias, C, Chi, Clo,
                                                     M, K, N, relu, Q, KV);
    }
}

static void gemm_ln(const __nv_bfloat16* Ahi, const __nv_bfloat16* Alo,
                    const __nv_bfloat16* Bhi, const __nv_bfloat16* Blo,
                    const float* bias, const __nv_bfloat16* resHi, const __nv_bfloat16* resLo,
                    const float* lng, const float* lnb,
                    __nv_bfloat16* outHi, __nv_bfloat16* outLo, int M, int K) {
    cudaFuncSetAttribute(gemm_ln_kernel, cudaFuncAttributeMaxDynamicSharedMemorySize, GEMM_SMEM);
    dim3 grid((M + 127) / 128, 1);
    gemm_ln_kernel<<<grid, 256, GEMM_SMEM>>>(Ahi, Alo, Bhi, Blo, bias, resHi, resLo,
                                             lng, lnb, outHi, outLo, M, K);
}

// ---------------- SIMT fallback GEMM (small N readout tail) ----------------
#define BMg 64
#define BNg 64
#define BKg 16
__global__ void __launch_bounds__(256) gemm_kernel(
    const float* __restrict__ A, const float* __restrict__ B,
    const float* __restrict__ bias, float* __restrict__ C, int M, int K, int N, int relu) {
    __shared__ float As[BKg][BMg + 1];
    __shared__ float Bs[BKg][BNg];

    int t = threadIdx.x;
    int m0 = blockIdx.x * BMg;
    int n0 = blockIdx.y * BNg;
    int ty = t >> 4;
    int tx = t & 15;

    int arow = t >> 2;
    int akc = (t & 3) * 4;
    int brow = t >> 4;
    int bnc = (t & 15) * 4;

    unsigned long long acc[4][2];
#pragma unroll
    for (int i = 0; i < 4; i++) { acc[i][0] = 0ull; acc[i][1] = 0ull; }

    for (int k0 = 0; k0 < K; k0 += BKg) {
        float4 av = make_float4(0.f, 0.f, 0.f, 0.f);
        if (m0 + arow < M) av = *(const float4*)&A[(size_t)(m0 + arow) * K + k0 + akc];
        As[akc + 0][arow] = av.x;
        As[akc + 1][arow] = av.y;
        As[akc + 2][arow] = av.z;
        As[akc + 3][arow] = av.w;

        float4 bv = make_float4(0.f, 0.f, 0.f, 0.f);
        if (n0 + bnc < N) bv = *(const float4*)&B[(size_t)(k0 + brow) * N + n0 + bnc];
        *(float4*)&Bs[brow][bnc] = bv;

        __syncthreads();
#pragma unroll
        for (int kk = 0; kk < BKg; kk++) {
            unsigned long long b0 = *(const unsigned long long*)&Bs[kk][tx * 4];
            unsigned long long b1 = *(const unsigned long long*)&Bs[kk][tx * 4 + 2];
            const float* ap = &As[kk][ty * 4];
#pragma unroll
            for (int i = 0; i < 4; i++) {
                unsigned long long aa = pack2(ap[i]);
                fma2(acc[i][0], aa, b0, acc[i][0]);
                fma2(acc[i][1], aa, b1, acc[i][1]);
            }
        }
        __syncthreads();
    }

#pragma unroll
    for (int i = 0; i < 4; i++) {
        int m = m0 + ty * 4 + i;
        if (m >= M) continue;
        float vals[4];
        unpack2(acc[i][0], vals[0], vals[1]);
        unpack2(acc[i][1], vals[2], vals[3]);
#pragma unroll
        for (int j = 0; j < 4; j++) {
            int n = n0 + tx * 4 + j;
            if (n >= N) continue;
            float val = vals[j];
            if (bias) val += bias[n];
            if (relu) val = fmaxf(val, 0.0f);
            C[(size_t)m * N + n] = val;
        }
    }
}

static void gemm_simt(const float* A, const float* B, const float* bias,
                      float* C, int M, int K, int N, int relu) {
    dim3 grid((M + BMg - 1) / BMg, (N + BNg - 1) / BNg);
    gemm_kernel<<<grid, 256>>>(A, B, bias, C, M, K, N, relu);
}

// ---------------- driver ----------------
extern "C" void kernel_launch(void* const* d_in, const int* in_sizes, int n_in,
                              void* d_out, int out_size) {
    const int* feat = (const int*)d_in[0];
    const int* esrc = (const int*)d_in[1];
    const int* edst = (const int*)d_in[2];
    const float* emb = (const float*)d_in[3];
    const float* Wq = (const float*)d_in[4];
    const float* Wk = (const float*)d_in[5];
    const float* Wv = (const float*)d_in[6];
    const float* Wo = (const float*)d_in[7];
    const float* bo = (const float*)d_in[8];
    const float* ln1_g = (const float*)d_in[9];
    const float* ln1_b = (const float*)d_in[10];
    const float* W1 = (const float*)d_in[11];
    const float* b1 = (const float*)d_in[12];
    const float* W2 = (const float*)d_in[13];
    const float* b2 = (const float*)d_in[14];
    const float* ln2_g = (const float*)d_in[15];
    const float* ln2_b = (const float*)d_in[16];
    const float* mW0 = (const float*)d_in[17];
    const float* mb0 = (const float*)d_in[18];
    const float* mW1 = (const float*)d_in[19];
    const float* mb1 = (const float*)d_in[20];
    const float* mW2 = (const float*)d_in[21];
    const float* mb2 = (const float*)d_in[22];
    float* out = (float*)d_out;

    float *q, *t0, *t1;
    int* rp;
    __nv_bfloat16 *kv;
    __nv_bfloat16 *h_hi, *h_lo, *attn_hi, *attn_lo, *mid_hi, *mid_lo;
    __nv_bfloat16 *wqkv_hi, *wqkv_lo, *wo_hi, *wo_lo, *w1_hi, *w1_lo, *w2_hi, *w2_lo, *m0_hi, *m0_lo;
    cudaGetSymbolAddress((void**)&q, g_q);
    cudaGetSymbolAddress((void**)&kv, g_kv);
    cudaGetSymbolAddress((void**)&t0, g_t0);
    cudaGetSymbolAddress((void**)&t1, g_t1);
    cudaGetSymbolAddress((void**)&rp, g_rowptr);
    cudaGetSymbolAddress((void**)&h_hi, g_h_hi);
    cudaGetSymbolAddress((void**)&h_lo, g_h_lo);
    cudaGetSymbolAddress((void**)&attn_hi, g_attn_hi);
    cudaGetSymbolAddress((void**)&attn_lo, g_attn_lo);
    cudaGetSymbolAddress((void**)&mid_hi, g_mid_hi);
    cudaGetSymbolAddress((void**)&mid_lo, g_mid_lo);
    cudaGetSymbolAddress((void**)&wqkv_hi, g_wqkv_hi);
    cudaGetSymbolAddress((void**)&wqkv_lo, g_wqkv_lo);
    cudaGetSymbolAddress((void**)&wo_hi, g_wo_hi);
    cudaGetSymbolAddress((void**)&wo_lo, g_wo_lo);
    cudaGetSymbolAddress((void**)&w1_hi, g_w1_hi);
    cudaGetSymbolAddress((void**)&w1_lo, g_w1_lo);
    cudaGetSymbolAddress((void**)&w2_hi, g_w2_hi);
    cudaGetSymbolAddress((void**)&w2_lo, g_w2_lo);
    cudaGetSymbolAddress((void**)&m0_hi, g_m0_hi);
    cudaGetSymbolAddress((void**)&m0_lo, g_m0_lo);

    // launch 1: square weights + readout m0
    {
        int tot = 4 * SQ_TOT + HID * 64;
        splitw_a_kernel<<<(tot + 255) / 256, 256>>>(Wq, Wk, Wv, Wo, mW0, wqkv_hi, wqkv_lo,
                                                    wo_hi, wo_lo, m0_hi, m0_lo);
    }
    // launch 2: FFN weights
    {
        int tot = 2 * RT_TOT;
        splitw_b_kernel<<<(tot + 255) / 256, 256>>>(W1, W2, w1_hi, w1_lo, w2_hi, w2_lo);
    }

    int warp_threads = N_NODES * 32;
    int wblocks = (warp_threads + 255) / 256;

    // launch 3
    rowptr_kernel<<<(N_NODES + 1 + 255) / 256, 256>>>(edst, rp);
    // launch 4
    embed_kernel<<<wblocks, 256>>>(feat, emb, h_hi, h_lo);

    for (int l = 0; l < N_LAYERS; l++) {
        const __nv_bfloat16* wqkvh = wqkv_hi + (size_t)l * 3 * HID * HID;
        const __nv_bfloat16* wqkvl = wqkv_lo + (size_t)l * 3 * HID * HID;
        const __nv_bfloat16* woh = wo_hi + (size_t)l * HID * HID;
        const __nv_bfloat16* wol = wo_lo + (size_t)l * HID * HID;
        const __nv_bfloat16* w1h = w1_hi + (size_t)l * 2 * HID * HID;
        const __nv_bfloat16* w1l = w1_lo + (size_t)l * 2 * HID * HID;
        const __nv_bfloat16* w2h = w2_hi + (size_t)l * HID * 2 * HID;
        const __nv_bfloat16* w2l = w2_lo + (size_t)l * HID * 2 * HID;

        // fused QKV -> q fp32 + kv bf16  (2-term: R11-vs-R12 measured marginal +1.9e-5)
        gemm_tc(2, h_hi, h_lo, wqkvh, wqkvl, nullptr, nullptr, nullptr, nullptr,
                N_NODES, HID, 3 * HID, 0, q, kv);

        attn_kernel<<<wblocks, 256>>>(q, kv, rp, esrc, attn_hi, attn_lo);

        // h = LN1(h + attn @ Wo + bo)   (3-term)
        gemm_ln(attn_hi, attn_lo, woh, wol, bo + l * HID, h_hi, h_lo,
                ln1_g + l * HID, ln1_b + l * HID, h_hi, h_lo, N_NODES, HID);
        // mid = relu(h @ W1 + b1)       (3-term: 2-term measured 1.9e-3 — unsafe)
        gemm_tc(3, h_hi, h_lo, w1h, w1l, b1 + l * 2 * HID, nullptr, mid_hi, mid_lo,
                N_NODES, HID, 2 * HID, 1);
        // h = LN2(h + mid @ W2 + b2)    (3-term)
        gemm_ln(mid_hi, mid_lo, w2h, w2l, b2 + l * HID, h_hi, h_lo,
                ln2_g + l * HID, ln2_b + l * HID, h_hi, h_lo, N_NODES, 2 * HID);
    }

    // readout: 128 -> 64 (tc, 3-term) -> 32 -> 16 (SIMT)
    gemm_tc(3, h_hi, h_lo, m0_hi, m0_lo, mb0, t0, nullptr, nullptr, N_NODES, HID, 64, 1);
    gemm_simt(t0, mW1, mb1, t1, N_NODES, 64, 32, 1);
    gemm_simt(t1, mW2, mb2, out, N_NODES, 32, N_CLASSES, 0);
}